// round 7
// baseline (speedup 1.0000x reference)
#include <cuda_runtime.h>

#define NE 150000
#define NN 50000
#define NT 100000
#define F  256
#define NLAYERS 4

// ---------------- scratch (allocation-free: __device__ globals) ----------------
__device__ float g_y0[(size_t)NE * F];   // x @ W0
__device__ float g_y2[(size_t)NE * F];   // x @ W2
__device__ float g_acc[(size_t)NE * F];  // d1, then += d2 (atomics)
__device__ float g_x[(size_t)NE * F];    // next-layer x (post ReLU)
__device__ float g_z[(size_t)NN * F];    // node buffer for B1
__device__ float g_w[(size_t)NT * F];    // triangle buffer for B2^T

// vector reduction (no return) — guaranteed sm_90+ PTX
__device__ __forceinline__ void red_add_f32x4(float* addr, float4 v) {
    asm volatile("red.global.add.v4.f32 [%0], {%1,%2,%3,%4};"
                 :: "l"(addr), "f"(v.x), "f"(v.y), "f"(v.z), "f"(v.w) : "memory");
}

// ---------------- fused triple GEMM: y0 = X@W0, acc = X@W1, y2 = X@W2 ----------
// 128x128 tile, BK=8, 256 threads, 8x8 outputs/thread in 2x2 blocks of 4x4.
__global__ __launch_bounds__(256, 2) void gemm3_kernel(
    const float* __restrict__ Xin,
    const float* __restrict__ W0, const float* __restrict__ W1,
    const float* __restrict__ W2)
{
    const float* X = Xin ? Xin : g_x;

    const int by  = blockIdx.y;          // 0..5
    const int mat = by >> 1;
    const float* W = (mat == 0) ? W0 : (mat == 1) ? W1 : W2;
    float* OUT     = (mat == 0) ? g_y0 : (mat == 1) ? g_acc : g_y2;
    const int n0 = (by & 1) * 128;
    const int m0 = blockIdx.x * 128;

    __shared__ float As[8][128];
    __shared__ float Bs[8][128];

    const int tid = threadIdx.x;
    const int tx  = tid & 15;            // 0..15 -> cols tx*4 and 64+tx*4
    const int ty  = tid >> 4;            // 0..15 -> rows ty*4 and 64+ty*4

    // A tile load mapping: 128 rows x 8 cols, one float4 per thread
    const int arow   = tid >> 1;         // 0..127
    const int acol   = (tid & 1) * 4;    // 0 or 4
    const int grow   = m0 + arow;
    const bool aval  = (grow < NE);
    const float* ap  = X + (size_t)grow * F + acol;

    // B tile load mapping: 8 rows x 128 cols, one float4 per thread
    const int brow   = tid >> 5;         // 0..7
    const int bcol   = (tid & 31) * 4;   // 0..124
    const float* bp  = W + (size_t)brow * F + n0 + bcol;

    float4 an = aval ? *(const float4*)ap : make_float4(0.f, 0.f, 0.f, 0.f);
    float4 bn = *(const float4*)bp;

    float c[2][2][4][4];
#pragma unroll
    for (int ri = 0; ri < 2; ri++)
#pragma unroll
        for (int rj = 0; rj < 2; rj++)
#pragma unroll
            for (int i = 0; i < 4; i++)
#pragma unroll
                for (int j = 0; j < 4; j++) c[ri][rj][i][j] = 0.f;

#pragma unroll 1
    for (int kt = 0; kt < F / 8; kt++) {
        As[acol + 0][arow] = an.x;
        As[acol + 1][arow] = an.y;
        As[acol + 2][arow] = an.z;
        As[acol + 3][arow] = an.w;
        *(float4*)&Bs[brow][bcol] = bn;
        __syncthreads();

        if (kt < F / 8 - 1) {
            an = aval ? *(const float4*)(ap + (kt + 1) * 8)
                      : make_float4(0.f, 0.f, 0.f, 0.f);
            bn = *(const float4*)(bp + (size_t)(kt + 1) * 8 * F);
        }

#pragma unroll
        for (int k = 0; k < 8; k++) {
            float4 a0 = *(const float4*)&As[k][ty * 4];
            float4 a1 = *(const float4*)&As[k][64 + ty * 4];
            float4 b0 = *(const float4*)&Bs[k][tx * 4];
            float4 b1 = *(const float4*)&Bs[k][64 + tx * 4];
            float A0[4] = {a0.x, a0.y, a0.z, a0.w};
            float A1[4] = {a1.x, a1.y, a1.z, a1.w};
            float B0[4] = {b0.x, b0.y, b0.z, b0.w};
            float B1[4] = {b1.x, b1.y, b1.z, b1.w};
#pragma unroll
            for (int i = 0; i < 4; i++)
#pragma unroll
                for (int j = 0; j < 4; j++) {
                    c[0][0][i][j] += A0[i] * B0[j];
                    c[0][1][i][j] += A0[i] * B1[j];
                    c[1][0][i][j] += A1[i] * B0[j];
                    c[1][1][i][j] += A1[i] * B1[j];
                }
        }
        __syncthreads();
    }

#pragma unroll
    for (int ri = 0; ri < 2; ri++)
#pragma unroll
        for (int i = 0; i < 4; i++) {
            int row = m0 + ri * 64 + ty * 4 + i;
            if (row < NE) {
#pragma unroll
                for (int rj = 0; rj < 2; rj++) {
                    float4 v = make_float4(c[ri][rj][i][0], c[ri][rj][i][1],
                                           c[ri][rj][i][2], c[ri][rj][i][3]);
                    *(float4*)&OUT[(size_t)row * F + n0 + rj * 64 + tx * 4] = v;
                }
            }
        }
}

// ---------------- graph ops ----------------------------------------------------
__global__ void zero_z_kernel() {
    int i = blockIdx.x * 256 + threadIdx.x;
    if (i < NN * F / 4) ((float4*)g_z)[i] = make_float4(0.f, 0.f, 0.f, 0.f);
}

// B1: z[u] -= y0[e], z[v] += y0[e]
__global__ void b1_scatter_kernel(const int* __restrict__ edge_nodes) {
    int t = blockIdx.x * 256 + threadIdx.x;
    if (t >= NE * 64) return;
    int e = t >> 6, c = (t & 63) * 4;
    float4 v = *(const float4*)&g_y0[(size_t)e * F + c];
    int u = edge_nodes[2 * e], w = edge_nodes[2 * e + 1];
    red_add_f32x4(&g_z[(size_t)u * F + c], make_float4(-v.x, -v.y, -v.z, -v.w));
    red_add_f32x4(&g_z[(size_t)w * F + c], v);
}

// B2^T: w[t] = sum_k s_k * y2[tri_edges[t,k]]
__global__ void b2t_gather_kernel(const int* __restrict__ tri_edges,
                                  const int* __restrict__ tri_signs) {
    int t = blockIdx.x * 256 + threadIdx.x;
    if (t >= NT * 64) return;
    int tri = t >> 6, c = (t & 63) * 4;
    int e0 = tri_edges[3 * tri], e1 = tri_edges[3 * tri + 1], e2 = tri_edges[3 * tri + 2];
    float s0 = (float)tri_signs[3 * tri];
    float s1 = (float)tri_signs[3 * tri + 1];
    float s2 = (float)tri_signs[3 * tri + 2];
    float4 v0 = *(const float4*)&g_y2[(size_t)e0 * F + c];
    float4 v1 = *(const float4*)&g_y2[(size_t)e1 * F + c];
    float4 v2 = *(const float4*)&g_y2[(size_t)e2 * F + c];
    float4 r = make_float4(s0 * v0.x + s1 * v1.x + s2 * v2.x,
                           s0 * v0.y + s1 * v1.y + s2 * v2.y,
                           s0 * v0.z + s1 * v1.z + s2 * v2.z,
                           s0 * v0.w + s1 * v1.w + s2 * v2.w);
    *(float4*)&g_w[(size_t)tri * F + c] = r;
}

// B2: acc[tri_edges[t,k]] += s_k * w[t]
__global__ void b2_scatter_kernel(const int* __restrict__ tri_edges,
                                  const int* __restrict__ tri_signs) {
    int t = blockIdx.x * 256 + threadIdx.x;
    if (t >= NT * 64) return;
    int tri = t >> 6, c = (t & 63) * 4;
    float4 w4 = *(const float4*)&g_w[(size_t)tri * F + c];
#pragma unroll
    for (int k = 0; k < 3; k++) {
        int e   = tri_edges[3 * tri + k];
        float s = (float)tri_signs[3 * tri + k];
        red_add_f32x4(&g_acc[(size_t)e * F + c],
                      make_float4(s * w4.x, s * w4.y, s * w4.z, s * w4.w));
    }
}

// x_new = relu(acc + z[v] - z[u])   (fuses B1^T, sum and ReLU)
__global__ void fuse_relu_kernel(const int* __restrict__ edge_nodes) {
    int t = blockIdx.x * 256 + threadIdx.x;
    if (t >= NE * 64) return;
    int e = t >> 6, c = (t & 63) * 4;
    int u = edge_nodes[2 * e], v = edge_nodes[2 * e + 1];
    float4 a  = *(const float4*)&g_acc[(size_t)e * F + c];
    float4 zu = *(const float4*)&g_z[(size_t)u * F + c];
    float4 zv = *(const float4*)&g_z[(size_t)v * F + c];
    float4 r = make_float4(fmaxf(a.x + zv.x - zu.x, 0.f),
                           fmaxf(a.y + zv.y - zu.y, 0.f),
                           fmaxf(a.z + zv.z - zu.z, 0.f),
                           fmaxf(a.w + zv.w - zu.w, 0.f));
    *(float4*)&g_x[(size_t)e * F + c] = r;
}

__global__ void zero_out_kernel(float* out) {
    int i = blockIdx.x * 256 + threadIdx.x;
    if (i < NN) out[i] = 0.f;
}

// final: y = x @ W0_L (GEMV) fused with B1 scatter into out
__global__ void gemv_scatter_kernel(const float* __restrict__ WL,
                                    const int* __restrict__ edge_nodes,
                                    float* __restrict__ out) {
    __shared__ float ws[F];
    int tid = threadIdx.x;
    ws[tid] = WL[tid];
    __syncthreads();
    int warp = tid >> 5, lane = tid & 31;
    int e = blockIdx.x * 8 + warp;
    if (e >= NE) return;
    float s = 0.f;
#pragma unroll
    for (int j = 0; j < 8; j++) {
        int c = j * 32 + lane;
        s += g_x[(size_t)e * F + c] * ws[c];
    }
#pragma unroll
    for (int o = 16; o; o >>= 1) s += __shfl_xor_sync(0xffffffffu, s, o);
    if (lane == 0) {
        int u = edge_nodes[2 * e], v = edge_nodes[2 * e + 1];
        atomicAdd(&out[u], -s);
        atomicAdd(&out[v], s);
    }
}

// ---------------- launcher ------------------------------------------------------
extern "C" void kernel_launch(void* const* d_in, const int* in_sizes, int n_in,
                              void* d_out, int out_size) {
    const float* x        = (const float*)d_in[0];
    const float* W0s      = (const float*)d_in[1];
    const float* W1s      = (const float*)d_in[2];
    const float* W2s      = (const float*)d_in[3];
    const float* WL       = (const float*)d_in[4];
    const int* edge_nodes = (const int*)d_in[5];
    const int* tri_edges  = (const int*)d_in[6];
    const int* tri_signs  = (const int*)d_in[7];
    float* out            = (float*)d_out;

    const int mtiles = (NE + 127) / 128;   // 1172

    for (int l = 0; l < NLAYERS; l++) {
        const float* xin = (l == 0) ? x : nullptr;   // nullptr -> kernel uses g_x
        gemm3_kernel<<<dim3(mtiles, 6), 256>>>(xin,
            W0s + (size_t)l * F * F, W1s + (size_t)l * F * F, W2s + (size_t)l * F * F);
        zero_z_kernel<<<(NN * F / 4 + 255) / 256, 256>>>();
        b1_scatter_kernel<<<(NE * 64 + 255) / 256, 256>>>(edge_nodes);
        b2t_gather_kernel<<<(NT * 64 + 255) / 256, 256>>>(tri_edges, tri_signs);
        b2_scatter_kernel<<<(NT * 64 + 255) / 256, 256>>>(tri_edges, tri_signs);
        fuse_relu_kernel<<<(NE * 64 + 255) / 256, 256>>>(edge_nodes);
    }
    zero_out_kernel<<<(NN + 255) / 256, 256>>>(out);
    gemv_scatter_kernel<<<(NE + 7) / 8, 256>>>(WL, edge_nodes, out);
}

// round 10
// speedup vs baseline: 1.6429x; 1.6429x over previous
#include <cuda_runtime.h>
#include <cuda_bf16.h>
#include <cstdint>

#define NE 150000
#define NN 50000
#define NT 100000
#define F  256
#define NLAYERS 4

// ---------------- scratch (allocation-free: __device__ globals) ----------------
__device__ float g_y0[(size_t)NE * F];   // x @ W0
__device__ float g_y2[(size_t)NE * F];   // x @ W2
__device__ float g_acc[(size_t)NE * F];  // d1, then += d2 (atomics)
__device__ float g_x[(size_t)NE * F];    // final-layer x (fp32, for GEMV)
__device__ float g_z[(size_t)NN * F];    // node buffer for B1
__device__ float g_w[(size_t)NT * F];    // triangle buffer for B2^T

// bf16 split operands for the tensor-core GEMM
__device__ __align__(16) __nv_bfloat16 g_x_hi[(size_t)NE * F];
__device__ __align__(16) __nv_bfloat16 g_x_lo[(size_t)NE * F];
__device__ __align__(16) __nv_bfloat16 g_wt_hi[3 * F * F];   // [mat][n][k]
__device__ __align__(16) __nv_bfloat16 g_wt_lo[3 * F * F];

// ---------------- PTX helpers (all sm_80-era, valid on sm_103 baseline) --------
__device__ __forceinline__ void red_add_f32x4(float* addr, float4 v) {
    asm volatile("red.global.add.v4.f32 [%0], {%1,%2,%3,%4};"
                 :: "l"(addr), "f"(v.x), "f"(v.y), "f"(v.z), "f"(v.w) : "memory");
}

__device__ __forceinline__ uint32_t smem_u32(const void* p) {
    uint32_t a;
    asm("{ .reg .u64 t; cvta.to.shared.u64 t, %1; cvt.u32.u64 %0, t; }"
        : "=r"(a) : "l"(p));
    return a;
}

__device__ __forceinline__ void cp16(uint32_t dst, const void* src, bool valid) {
    int sz = valid ? 16 : 0;
    asm volatile("cp.async.ca.shared.global [%0], [%1], 16, %2;"
                 :: "r"(dst), "l"(src), "r"(sz) : "memory");
}
__device__ __forceinline__ void cp_commit() {
    asm volatile("cp.async.commit_group;" ::: "memory");
}
__device__ __forceinline__ void cp_wait1() {
    asm volatile("cp.async.wait_group 1;" ::: "memory");
}

__device__ __forceinline__ void ldsm4(uint32_t& r0, uint32_t& r1, uint32_t& r2,
                                      uint32_t& r3, uint32_t addr) {
    asm volatile("ldmatrix.sync.aligned.m8n8.x4.shared.b16 {%0,%1,%2,%3}, [%4];"
                 : "=r"(r0), "=r"(r1), "=r"(r2), "=r"(r3) : "r"(addr));
}

__device__ __forceinline__ void mma_bf16(float* c, const uint32_t* a,
                                         uint32_t b0, uint32_t b1) {
    asm volatile(
        "mma.sync.aligned.m16n8k16.row.col.f32.bf16.bf16.f32 "
        "{%0,%1,%2,%3}, {%4,%5,%6,%7}, {%8,%9}, {%0,%1,%2,%3};"
        : "+f"(c[0]), "+f"(c[1]), "+f"(c[2]), "+f"(c[3])
        : "r"(a[0]), "r"(a[1]), "r"(a[2]), "r"(a[3]), "r"(b0), "r"(b1));
}

// ---------------- tensor-core GEMM: OUT[mat] = X @ W[mat], bf16x3 split --------
// Block: 128(M) x 128(N), BK=32, 256 threads = 8 warps as 2(M) x 4(N).
// Smem row = [hi 64B | lo 64B] = 128B with SW128 xor swizzle; 2-stage cp.async.
#define STAGE_BYTES 32768   /* A 16KB + B 16KB */
#define GSMEM_TOTAL 65536

__global__ __launch_bounds__(256, 1) void gemm_tc_kernel() {
    extern __shared__ char smem[];
    const uint32_t smem_base = smem_u32(smem);

    const int tid  = threadIdx.x;
    const int lane = tid & 31;
    const int w    = tid >> 5;
    const int wm   = w & 1;          // 0..1 -> 64 M-rows each
    const int wn   = w >> 1;         // 0..3 -> 32 N-cols each

    const int mat = blockIdx.y >> 1;
    const int n0  = (blockIdx.y & 1) * 128;
    const int m0  = blockIdx.x * 128;

    float* OUT = (mat == 0) ? g_y0 : (mat == 1) ? g_acc : g_y2;
    const __nv_bfloat16* Bh = g_wt_hi + (size_t)mat * 65536 + (size_t)n0 * 256;
    const __nv_bfloat16* Bl = g_wt_lo + (size_t)mat * 65536 + (size_t)n0 * 256;

    // ldmatrix lane address decomposition (same pattern for A and B)
    const int g     = lane >> 3;                       // 0..3
    const int rlane = (lane & 7) + ((g & 1) << 3);     // row-in-frag 0..15
    const int khalf = g >> 1;                          // 0..1 (k 16B chunk)

    float acc[4][4][4];
#pragma unroll
    for (int mi = 0; mi < 4; mi++)
#pragma unroll
        for (int nj = 0; nj < 4; nj++)
#pragma unroll
            for (int r = 0; r < 4; r++) acc[mi][nj][r] = 0.f;

    // ---- tile loader: stage s, K-chunk kc (kc in 0..7, 32 cols each) ----
    auto load_tiles = [&](int s, int kc) {
        uint32_t sA = smem_base + s * STAGE_BYTES;
        uint32_t sB = sA + 16384;
#pragma unroll
        for (int i = 0; i < 4; i++) {               // A: 1024 16B chunks
            int ch  = tid + i * 256;
            int row = ch >> 3, pos = ch & 7;        // pos 0-3 hi, 4-7 lo
            int split = pos >> 2, p4 = pos & 3;
            int grow = m0 + row;
            bool v = (grow < NE);
            int r = v ? grow : 0;
            const __nv_bfloat16* src =
                (split ? g_x_lo : g_x_hi) + (size_t)r * F + kc * 32 + p4 * 8;
            uint32_t dst = sA + row * 128 + ((pos ^ (row & 7)) << 4);
            cp16(dst, src, v);
        }
#pragma unroll
        for (int i = 0; i < 4; i++) {               // B: 1024 16B chunks
            int ch  = tid + i * 256;
            int row = ch >> 3, pos = ch & 7;
            int split = pos >> 2, p4 = pos & 3;
            const __nv_bfloat16* src =
                (split ? Bl : Bh) + (size_t)row * 256 + kc * 32 + p4 * 8;
            uint32_t dst = sB + row * 128 + ((pos ^ (row & 7)) << 4);
            cp16(dst, src, true);
        }
    };

    load_tiles(0, 0); cp_commit();
    load_tiles(1, 1); cp_commit();

    for (int kc = 0; kc < 8; kc++) {
        cp_wait1();
        __syncthreads();

        const int st = kc & 1;
        uint32_t sA = smem_base + st * STAGE_BYTES;
        uint32_t sB = sA + 16384;

#pragma unroll
        for (int ks = 0; ks < 2; ks++) {
            uint32_t ah[4][4], al[4][4];
            uint32_t bh[2][4], bl[2][4];
            const int chH = ks * 2 + khalf;        // hi chunk idx 0..3
            const int chL = chH + 4;               // lo chunk idx 4..7
#pragma unroll
            for (int mi = 0; mi < 4; mi++) {
                int row = wm * 64 + mi * 16 + rlane;
                uint32_t base = sA + row * 128;
                ldsm4(ah[mi][0], ah[mi][1], ah[mi][2], ah[mi][3],
                      base + ((chH ^ (row & 7)) << 4));
                ldsm4(al[mi][0], al[mi][1], al[mi][2], al[mi][3],
                      base + ((chL ^ (row & 7)) << 4));
            }
#pragma unroll
            for (int j = 0; j < 2; j++) {
                int row = wn * 32 + j * 16 + rlane;
                uint32_t base = sB + row * 128;
                ldsm4(bh[j][0], bh[j][1], bh[j][2], bh[j][3],
                      base + ((chH ^ (row & 7)) << 4));
                ldsm4(bl[j][0], bl[j][1], bl[j][2], bl[j][3],
                      base + ((chL ^ (row & 7)) << 4));
            }
#pragma unroll
            for (int mi = 0; mi < 4; mi++)
#pragma unroll
                for (int nj = 0; nj < 4; nj++) {
                    int j = nj >> 1, o = nj & 1;
                    mma_bf16(acc[mi][nj], ah[mi], bh[j][o], bh[j][o + 2]); // hi*hi
                    mma_bf16(acc[mi][nj], ah[mi], bl[j][o], bl[j][o + 2]); // hi*lo
                    mma_bf16(acc[mi][nj], al[mi], bh[j][o], bh[j][o + 2]); // lo*hi
                }
        }

        __syncthreads();
        if (kc + 2 < 8) load_tiles(st, kc + 2);
        cp_commit();
    }

    // ---- epilogue: direct float2 stores (32B sectors fully used) ----
    const int crow = lane >> 2;
    const int ccol = (lane & 3) * 2;
#pragma unroll
    for (int mi = 0; mi < 4; mi++) {
#pragma unroll
        for (int nj = 0; nj < 4; nj++) {
            int gr = m0 + wm * 64 + mi * 16 + crow;
            int gc = n0 + wn * 32 + nj * 8 + ccol;
            if (gr < NE)
                *(float2*)&OUT[(size_t)gr * F + gc] =
                    make_float2(acc[mi][nj][0], acc[mi][nj][1]);
            if (gr + 8 < NE)
                *(float2*)&OUT[(size_t)(gr + 8) * F + gc] =
                    make_float2(acc[mi][nj][2], acc[mi][nj][3]);
        }
    }
}

// ---------------- bf16 split conversion ----------------------------------------
__device__ __forceinline__ void split2(float v, unsigned short& h, unsigned short& l) {
    __nv_bfloat16 hb = __float2bfloat16(v);
    float hf = __bfloat162float(hb);
    __nv_bfloat16 lb = __float2bfloat16(v - hf);
    h = reinterpret_cast<unsigned short&>(hb);
    l = reinterpret_cast<unsigned short&>(lb);
}

__device__ __forceinline__ void store_split4(size_t off, float4 r) {
    unsigned short h[4], l[4];
    split2(r.x, h[0], l[0]); split2(r.y, h[1], l[1]);
    split2(r.z, h[2], l[2]); split2(r.w, h[3], l[3]);
    uint2 H = make_uint2((uint32_t)h[0] | ((uint32_t)h[1] << 16),
                         (uint32_t)h[2] | ((uint32_t)h[3] << 16));
    uint2 L = make_uint2((uint32_t)l[0] | ((uint32_t)l[1] << 16),
                         (uint32_t)l[2] | ((uint32_t)l[3] << 16));
    *(uint2*)&g_x_hi[off] = H;
    *(uint2*)&g_x_lo[off] = L;
}

__global__ void convert_x_kernel(const float* __restrict__ x) {
    int t = blockIdx.x * 256 + threadIdx.x;
    if (t >= NE * 64) return;
    int e = t >> 6, c = (t & 63) * 4;
    float4 v = *(const float4*)&x[(size_t)e * F + c];
    store_split4((size_t)e * F + c, v);
}

// g_wt_{hi,lo}[mat][n][k] = split(W_mat[k][n])
__global__ void convert_w_kernel(const float* __restrict__ W0,
                                 const float* __restrict__ W1,
                                 const float* __restrict__ W2) {
    int t = blockIdx.x * 256 + threadIdx.x;
    if (t >= 3 * F * F) return;
    int mat = t >> 16, r = t & 65535, n = r >> 8, k = r & 255;
    const float* W = (mat == 0) ? W0 : (mat == 1) ? W1 : W2;
    float v = W[k * F + n];
    unsigned short h, l;
    split2(v, h, l);
    g_wt_hi[t] = reinterpret_cast<__nv_bfloat16&>(h);
    g_wt_lo[t] = reinterpret_cast<__nv_bfloat16&>(l);
}

// ---------------- graph ops ----------------------------------------------------
__global__ void zero_z_kernel() {
    int i = blockIdx.x * 256 + threadIdx.x;
    if (i < NN * F / 4) ((float4*)g_z)[i] = make_float4(0.f, 0.f, 0.f, 0.f);
}

__global__ void b1_scatter_kernel(const int* __restrict__ edge_nodes) {
    int t = blockIdx.x * 256 + threadIdx.x;
    if (t >= NE * 64) return;
    int e = t >> 6, c = (t & 63) * 4;
    float4 v = *(const float4*)&g_y0[(size_t)e * F + c];
    int u = edge_nodes[2 * e], w = edge_nodes[2 * e + 1];
    red_add_f32x4(&g_z[(size_t)u * F + c], make_float4(-v.x, -v.y, -v.z, -v.w));
    red_add_f32x4(&g_z[(size_t)w * F + c], v);
}

__global__ void b2t_gather_kernel(const int* __restrict__ tri_edges,
                                  const int* __restrict__ tri_signs) {
    int t = blockIdx.x * 256 + threadIdx.x;
    if (t >= NT * 64) return;
    int tri = t >> 6, c = (t & 63) * 4;
    int e0 = tri_edges[3 * tri], e1 = tri_edges[3 * tri + 1], e2 = tri_edges[3 * tri + 2];
    float s0 = (float)tri_signs[3 * tri];
    float s1 = (float)tri_signs[3 * tri + 1];
    float s2 = (float)tri_signs[3 * tri + 2];
    float4 v0 = *(const float4*)&g_y2[(size_t)e0 * F + c];
    float4 v1 = *(const float4*)&g_y2[(size_t)e1 * F + c];
    float4 v2 = *(const float4*)&g_y2[(size_t)e2 * F + c];
    float4 r = make_float4(s0 * v0.x + s1 * v1.x + s2 * v2.x,
                           s0 * v0.y + s1 * v1.y + s2 * v2.y,
                           s0 * v0.z + s1 * v1.z + s2 * v2.z,
                           s0 * v0.w + s1 * v1.w + s2 * v2.w);
    *(float4*)&g_w[(size_t)tri * F + c] = r;
}

__global__ void b2_scatter_kernel(const int* __restrict__ tri_edges,
                                  const int* __restrict__ tri_signs) {
    int t = blockIdx.x * 256 + threadIdx.x;
    if (t >= NT * 64) return;
    int tri = t >> 6, c = (t & 63) * 4;
    float4 w4 = *(const float4*)&g_w[(size_t)tri * F + c];
#pragma unroll
    for (int k = 0; k < 3; k++) {
        int e   = tri_edges[3 * tri + k];
        float s = (float)tri_signs[3 * tri + k];
        red_add_f32x4(&g_acc[(size_t)e * F + c],
                      make_float4(s * w4.x, s * w4.y, s * w4.z, s * w4.w));
    }
}

// x_new = relu(acc + z[v] - z[u]); writes bf16 hi/lo splits (fp32 on last layer)
__global__ void fuse_relu_kernel(const int* __restrict__ edge_nodes, int write_f32) {
    int t = blockIdx.x * 256 + threadIdx.x;
    if (t >= NE * 64) return;
    int e = t >> 6, c = (t & 63) * 4;
    int u = edge_nodes[2 * e], v = edge_nodes[2 * e + 1];
    float4 a  = *(const float4*)&g_acc[(size_t)e * F + c];
    float4 zu = *(const float4*)&g_z[(size_t)u * F + c];
    float4 zv = *(const float4*)&g_z[(size_t)v * F + c];
    float4 r = make_float4(fmaxf(a.x + zv.x - zu.x, 0.f),
                           fmaxf(a.y + zv.y - zu.y, 0.f),
                           fmaxf(a.z + zv.z - zu.z, 0.f),
                           fmaxf(a.w + zv.w - zu.w, 0.f));
    size_t off = (size_t)e * F + c;
    if (write_f32) {
        *(float4*)&g_x[off] = r;
    } else {
        store_split4(off, r);
    }
}

__global__ void zero_out_kernel(float* out) {
    int i = blockIdx.x * 256 + threadIdx.x;
    if (i < NN) out[i] = 0.f;
}

__global__ void gemv_scatter_kernel(const float* __restrict__ WL,
                                    const int* __restrict__ edge_nodes,
                                    float* __restrict__ out) {
    __shared__ float ws[F];
    int tid = threadIdx.x;
    ws[tid] = WL[tid];
    __syncthreads();
    int warp = tid >> 5, lane = tid & 31;
    int e = blockIdx.x * 8 + warp;
    if (e >= NE) return;
    float s = 0.f;
#pragma unroll
    for (int j = 0; j < 8; j++) {
        int c = j * 32 + lane;
        s += g_x[(size_t)e * F + c] * ws[c];
    }
#pragma unroll
    for (int o = 16; o; o >>= 1) s += __shfl_xor_sync(0xffffffffu, s, o);
    if (lane == 0) {
        int u = edge_nodes[2 * e], v = edge_nodes[2 * e + 1];
        atomicAdd(&out[u], -s);
        atomicAdd(&out[v], s);
    }
}

// ---------------- launcher ------------------------------------------------------
extern "C" void kernel_launch(void* const* d_in, const int* in_sizes, int n_in,
                              void* d_out, int out_size) {
    const float* x        = (const float*)d_in[0];
    const float* W0s      = (const float*)d_in[1];
    const float* W1s      = (const float*)d_in[2];
    const float* W2s      = (const float*)d_in[3];
    const float* WL       = (const float*)d_in[4];
    const int* edge_nodes = (const int*)d_in[5];
    const int* tri_edges  = (const int*)d_in[6];
    const int* tri_signs  = (const int*)d_in[7];
    float* out            = (float*)d_out;

    cudaFuncSetAttribute(gemm_tc_kernel,
                         cudaFuncAttributeMaxDynamicSharedMemorySize, GSMEM_TOTAL);

    const int mtiles = (NE + 127) / 128;   // 1172

    convert_x_kernel<<<(NE * 64 + 255) / 256, 256>>>(x);

    for (int l = 0; l < NLAYERS; l++) {
        convert_w_kernel<<<(3 * F * F + 255) / 256, 256>>>(
            W0s + (size_t)l * F * F, W1s + (size_t)l * F * F, W2s + (size_t)l * F * F);
        gemm_tc_kernel<<<dim3(mtiles, 6), 256, GSMEM_TOTAL>>>();
        zero_z_kernel<<<(NN * F / 4 + 255) / 256, 256>>>();
        b1_scatter_kernel<<<(NE * 64 + 255) / 256, 256>>>(edge_nodes);
        b2t_gather_kernel<<<(NT * 64 + 255) / 256, 256>>>(tri_edges, tri_signs);
        b2_scatter_kernel<<<(NT * 64 + 255) / 256, 256>>>(tri_edges, tri_signs);
        fuse_relu_kernel<<<(NE * 64 + 255) / 256, 256>>>(edge_nodes,
                                                         (l == NLAYERS - 1) ? 1 : 0);
    }
    zero_out_kernel<<<(NN + 255) / 256, 256>>>(out);
    gemv_scatter_kernel<<<(NE + 7) / 8, 256>>>(WL, edge_nodes, out);
}

// round 11
// speedup vs baseline: 1.6693x; 1.0161x over previous
#include <cuda_runtime.h>
#include <cuda_bf16.h>
#include <cstdint>

#define NE 150000
#define NN 50000
#define NT 100000
#define F  256
#define NLAYERS 4

// ---------------- scratch (allocation-free: __device__ globals) ----------------
__device__ float g_y2[(size_t)NE * F];   // x @ W2
__device__ float g_acc[(size_t)NE * F];  // d1, then += d2 (atomics)
__device__ float g_x[(size_t)NE * F];    // final-layer x (fp32, for GEMV)
__device__ float g_z[(size_t)NN * F];    // node buffer for B1 (atomics)

// bf16 split operands for the tensor-core GEMM
__device__ __align__(16) __nv_bfloat16 g_x_hi[(size_t)NE * F];
__device__ __align__(16) __nv_bfloat16 g_x_lo[(size_t)NE * F];
__device__ __align__(16) __nv_bfloat16 g_wt_hi[NLAYERS * 3 * F * F]; // [l*3+mat][n][k]
__device__ __align__(16) __nv_bfloat16 g_wt_lo[NLAYERS * 3 * F * F];

// ---------------- PTX helpers (all sm_80-era, valid on sm_103 baseline) --------
__device__ __forceinline__ void red_add_f32x4(float* addr, float4 v) {
    asm volatile("red.global.add.v4.f32 [%0], {%1,%2,%3,%4};"
                 :: "l"(addr), "f"(v.x), "f"(v.y), "f"(v.z), "f"(v.w) : "memory");
}

__device__ __forceinline__ uint32_t smem_u32(const void* p) {
    uint32_t a;
    asm("{ .reg .u64 t; cvta.to.shared.u64 t, %1; cvt.u32.u64 %0, t; }"
        : "=r"(a) : "l"(p));
    return a;
}

__device__ __forceinline__ void cp16(uint32_t dst, const void* src, bool valid) {
    int sz = valid ? 16 : 0;
    asm volatile("cp.async.ca.shared.global [%0], [%1], 16, %2;"
                 :: "r"(dst), "l"(src), "r"(sz) : "memory");
}
__device__ __forceinline__ void cp_commit() {
    asm volatile("cp.async.commit_group;" ::: "memory");
}
__device__ __forceinline__ void cp_wait1() {
    asm volatile("cp.async.wait_group 1;" ::: "memory");
}

__device__ __forceinline__ void ldsm4(uint32_t& r0, uint32_t& r1, uint32_t& r2,
                                      uint32_t& r3, uint32_t addr) {
    asm volatile("ldmatrix.sync.aligned.m8n8.x4.shared.b16 {%0,%1,%2,%3}, [%4];"
                 : "=r"(r0), "=r"(r1), "=r"(r2), "=r"(r3) : "r"(addr));
}

__device__ __forceinline__ void mma_bf16(float* c, const uint32_t* a,
                                         uint32_t b0, uint32_t b1) {
    asm volatile(
        "mma.sync.aligned.m16n8k16.row.col.f32.bf16.bf16.f32 "
        "{%0,%1,%2,%3}, {%4,%5,%6,%7}, {%8,%9}, {%0,%1,%2,%3};"
        : "+f"(c[0]), "+f"(c[1]), "+f"(c[2]), "+f"(c[3])
        : "r"(a[0]), "r"(a[1]), "r"(a[2]), "r"(a[3]), "r"(b0), "r"(b1));
}

// ---------------- tensor-core GEMM: bf16x3 split, 3-stage cp.async -------------
// Block: 128(M) x 128(N), BK=32, 256 threads = 8 warps as 2(M) x 4(N).
// Smem row = [hi 64B | lo 64B] = 128B with SW128 xor swizzle.
// mat0 epilogue fuses the B1 scatter (red.add into g_z), mat1 -> g_acc,
// mat2 -> g_y2.
#define STAGE_BYTES 32768   /* A 16KB + B 16KB */
#define GSMEM_TOTAL (3 * STAGE_BYTES)

__global__ __launch_bounds__(256, 1) void gemm_tc_kernel(
    int layer, const int* __restrict__ edge_nodes)
{
    extern __shared__ char smem[];
    const uint32_t smem_base = smem_u32(smem);

    const int tid  = threadIdx.x;
    const int lane = tid & 31;
    const int w    = tid >> 5;
    const int wm   = w & 1;          // 0..1 -> 64 M-rows each
    const int wn   = w >> 1;         // 0..3 -> 32 N-cols each

    const int mat = blockIdx.y >> 1;
    const int n0  = (blockIdx.y & 1) * 128;
    const int m0  = blockIdx.x * 128;

    const size_t wofs = (size_t)(layer * 3 + mat) * 65536 + (size_t)n0 * 256;
    const __nv_bfloat16* Bh = g_wt_hi + wofs;
    const __nv_bfloat16* Bl = g_wt_lo + wofs;

    // ldmatrix lane address decomposition (same pattern for A and B)
    const int g     = lane >> 3;                       // 0..3
    const int rlane = (lane & 7) + ((g & 1) << 3);     // row-in-frag 0..15
    const int khalf = g >> 1;                          // 0..1 (k 16B chunk)

    float acc[4][4][4];
#pragma unroll
    for (int mi = 0; mi < 4; mi++)
#pragma unroll
        for (int nj = 0; nj < 4; nj++)
#pragma unroll
            for (int r = 0; r < 4; r++) acc[mi][nj][r] = 0.f;

    // ---- tile loader: stage s, K-chunk kc (kc in 0..7, 32 cols each) ----
    auto load_tiles = [&](int s, int kc) {
        uint32_t sA = smem_base + s * STAGE_BYTES;
        uint32_t sB = sA + 16384;
#pragma unroll
        for (int i = 0; i < 4; i++) {               // A: 1024 16B chunks
            int ch  = tid + i * 256;
            int row = ch >> 3, pos = ch & 7;        // pos 0-3 hi, 4-7 lo
            int split = pos >> 2, p4 = pos & 3;
            int grow = m0 + row;
            bool v = (grow < NE);
            int r = v ? grow : 0;
            const __nv_bfloat16* src =
                (split ? g_x_lo : g_x_hi) + (size_t)r * F + kc * 32 + p4 * 8;
            uint32_t dst = sA + row * 128 + ((pos ^ (row & 7)) << 4);
            cp16(dst, src, v);
        }
#pragma unroll
        for (int i = 0; i < 4; i++) {               // B: 1024 16B chunks
            int ch  = tid + i * 256;
            int row = ch >> 3, pos = ch & 7;
            int split = pos >> 2, p4 = pos & 3;
            const __nv_bfloat16* src =
                (split ? Bl : Bh) + (size_t)row * 256 + kc * 32 + p4 * 8;
            uint32_t dst = sB + row * 128 + ((pos ^ (row & 7)) << 4);
            cp16(dst, src, true);
        }
    };

    load_tiles(0, 0); cp_commit();
    load_tiles(1, 1); cp_commit();

    for (int kc = 0; kc < 8; kc++) {
        cp_wait1();
        __syncthreads();

        // prefetch kc+2 into the stage consumed last iteration
        if (kc + 2 < 8) load_tiles((kc + 2) % 3, kc + 2);
        cp_commit();

        const int st = kc % 3;
        uint32_t sA = smem_base + st * STAGE_BYTES;
        uint32_t sB = sA + 16384;

#pragma unroll
        for (int ks = 0; ks < 2; ks++) {
            uint32_t ah[4][4], al[4][4];
            uint32_t bh[2][4], bl[2][4];
            const int chH = ks * 2 + khalf;        // hi chunk idx 0..3
            const int chL = chH + 4;               // lo chunk idx 4..7
#pragma unroll
            for (int mi = 0; mi < 4; mi++) {
                int row = wm * 64 + mi * 16 + rlane;
                uint32_t base = sA + row * 128;
                ldsm4(ah[mi][0], ah[mi][1], ah[mi][2], ah[mi][3],
                      base + ((chH ^ (row & 7)) << 4));
                ldsm4(al[mi][0], al[mi][1], al[mi][2], al[mi][3],
                      base + ((chL ^ (row & 7)) << 4));
            }
#pragma unroll
            for (int j = 0; j < 2; j++) {
                int row = wn * 32 + j * 16 + rlane;
                uint32_t base = sB + row * 128;
                ldsm4(bh[j][0], bh[j][1], bh[j][2], bh[j][3],
                      base + ((chH ^ (row & 7)) << 4));
                ldsm4(bl[j][0], bl[j][1], bl[j][2], bl[j][3],
                      base + ((chL ^ (row & 7)) << 4));
            }
#pragma unroll
            for (int mi = 0; mi < 4; mi++)
#pragma unroll
                for (int nj = 0; nj < 4; nj++) {
                    int j = nj >> 1, o = nj & 1;
                    mma_bf16(acc[mi][nj], ah[mi], bh[j][o], bh[j][o + 2]); // hi*hi
                    mma_bf16(acc[mi][nj], ah[mi], bl[j][o], bl[j][o + 2]); // hi*lo
                    mma_bf16(acc[mi][nj], al[mi], bh[j][o], bh[j][o + 2]); // lo*hi
                }
        }
        __syncthreads();
    }

    const int crow = lane >> 2;
    const int ccol = (lane & 3) * 2;

    if (mat == 0) {
        // ---- fused B1 scatter: z[u] -= y0, z[v] += y0 (red.v4 via lane pair) --
#pragma unroll
        for (int mi = 0; mi < 4; mi++) {
            int r0 = m0 + wm * 64 + mi * 16 + crow;
            int r1 = r0 + 8;
            int u0 = 0, v0 = 0, u1 = 0, v1 = 0;
            if (r0 < NE) { u0 = edge_nodes[2 * r0]; v0 = edge_nodes[2 * r0 + 1]; }
            if (r1 < NE) { u1 = edge_nodes[2 * r1]; v1 = edge_nodes[2 * r1 + 1]; }
            int gc = n0 + wn * 32 + (lane & 2) * 2;  // float4 col base (per pair)
#pragma unroll
            for (int nj = 0; nj < 4; nj++) {
                float x0 = acc[mi][nj][0], y0 = acc[mi][nj][1];
                float x1 = acc[mi][nj][2], y1 = acc[mi][nj][3];
                float px0 = __shfl_xor_sync(0xffffffffu, x0, 1);
                float py0 = __shfl_xor_sync(0xffffffffu, y0, 1);
                float px1 = __shfl_xor_sync(0xffffffffu, x1, 1);
                float py1 = __shfl_xor_sync(0xffffffffu, y1, 1);
                if (!(lane & 1)) {
                    int c = gc + nj * 8;
                    if (r0 < NE) {
                        float4 q = make_float4(x0, y0, px0, py0);
                        red_add_f32x4(&g_z[(size_t)u0 * F + c],
                                      make_float4(-q.x, -q.y, -q.z, -q.w));
                        red_add_f32x4(&g_z[(size_t)v0 * F + c], q);
                    }
                    if (r1 < NE) {
                        float4 q = make_float4(x1, y1, px1, py1);
                        red_add_f32x4(&g_z[(size_t)u1 * F + c],
                                      make_float4(-q.x, -q.y, -q.z, -q.w));
                        red_add_f32x4(&g_z[(size_t)v1 * F + c], q);
                    }
                }
            }
        }
    } else {
        float* OUT = (mat == 1) ? g_acc : g_y2;
#pragma unroll
        for (int mi = 0; mi < 4; mi++) {
#pragma unroll
            for (int nj = 0; nj < 4; nj++) {
                int gr = m0 + wm * 64 + mi * 16 + crow;
                int gc = n0 + wn * 32 + nj * 8 + ccol;
                if (gr < NE)
                    *(float2*)&OUT[(size_t)gr * F + gc] =
                        make_float2(acc[mi][nj][0], acc[mi][nj][1]);
                if (gr + 8 < NE)
                    *(float2*)&OUT[(size_t)(gr + 8) * F + gc] =
                        make_float2(acc[mi][nj][2], acc[mi][nj][3]);
            }
        }
    }
}

// ---------------- bf16 split conversion ----------------------------------------
__device__ __forceinline__ void split2(float v, unsigned short& h, unsigned short& l) {
    __nv_bfloat16 hb = __float2bfloat16(v);
    float hf = __bfloat162float(hb);
    __nv_bfloat16 lb = __float2bfloat16(v - hf);
    h = reinterpret_cast<unsigned short&>(hb);
    l = reinterpret_cast<unsigned short&>(lb);
}

__device__ __forceinline__ void store_split4(size_t off, float4 r) {
    unsigned short h[4], l[4];
    split2(r.x, h[0], l[0]); split2(r.y, h[1], l[1]);
    split2(r.z, h[2], l[2]); split2(r.w, h[3], l[3]);
    uint2 H = make_uint2((uint32_t)h[0] | ((uint32_t)h[1] << 16),
                         (uint32_t)h[2] | ((uint32_t)h[3] << 16));
    uint2 L = make_uint2((uint32_t)l[0] | ((uint32_t)l[1] << 16),
                         (uint32_t)l[2] | ((uint32_t)l[3] << 16));
    *(uint2*)&g_x_hi[off] = H;
    *(uint2*)&g_x_lo[off] = L;
}

__global__ void convert_x_kernel(const float* __restrict__ x) {
    int t = blockIdx.x * 256 + threadIdx.x;
    if (t >= NE * 64) return;
    int e = t >> 6, c = (t & 63) * 4;
    float4 v = *(const float4*)&x[(size_t)e * F + c];
    store_split4((size_t)e * F + c, v);
}

// all layers at once: g_wt_{hi,lo}[l*3+mat][n][k] = split(W_mat^l[k][n])
__global__ void convert_w_kernel(const float* __restrict__ W0,
                                 const float* __restrict__ W1,
                                 const float* __restrict__ W2) {
    int t = blockIdx.x * 256 + threadIdx.x;
    if (t >= NLAYERS * 3 * F * F) return;
    int lm = t >> 16, r = t & 65535, n = r >> 8, k = r & 255;
    int l = lm / 3, mat = lm % 3;
    const float* W = ((mat == 0) ? W0 : (mat == 1) ? W1 : W2) + (size_t)l * F * F;
    float v = W[k * F + n];
    unsigned short h, lo;
    split2(v, h, lo);
    g_wt_hi[t] = reinterpret_cast<__nv_bfloat16&>(h);
    g_wt_lo[t] = reinterpret_cast<__nv_bfloat16&>(lo);
}

// ---------------- graph ops ----------------------------------------------------
__global__ void zero_z_kernel() {
    int i = blockIdx.x * 256 + threadIdx.x;
    if (i < NN * F / 4) ((float4*)g_z)[i] = make_float4(0.f, 0.f, 0.f, 0.f);
}

// fused B2: w = sum_k s_k * y2[e_k]; acc[e_k] += s_k * w   (no g_w round trip)
__global__ void b2_fused_kernel(const int* __restrict__ tri_edges,
                                const int* __restrict__ tri_signs) {
    int t = blockIdx.x * 256 + threadIdx.x;
    if (t >= NT * 64) return;
    int tri = t >> 6, c = (t & 63) * 4;
    int e0 = tri_edges[3 * tri], e1 = tri_edges[3 * tri + 1], e2 = tri_edges[3 * tri + 2];
    float s0 = (float)tri_signs[3 * tri];
    float s1 = (float)tri_signs[3 * tri + 1];
    float s2 = (float)tri_signs[3 * tri + 2];
    float4 v0 = *(const float4*)&g_y2[(size_t)e0 * F + c];
    float4 v1 = *(const float4*)&g_y2[(size_t)e1 * F + c];
    float4 v2 = *(const float4*)&g_y2[(size_t)e2 * F + c];
    float4 wv = make_float4(s0 * v0.x + s1 * v1.x + s2 * v2.x,
                            s0 * v0.y + s1 * v1.y + s2 * v2.y,
                            s0 * v0.z + s1 * v1.z + s2 * v2.z,
                            s0 * v0.w + s1 * v1.w + s2 * v2.w);
    red_add_f32x4(&g_acc[(size_t)e0 * F + c],
                  make_float4(s0 * wv.x, s0 * wv.y, s0 * wv.z, s0 * wv.w));
    red_add_f32x4(&g_acc[(size_t)e1 * F + c],
                  make_float4(s1 * wv.x, s1 * wv.y, s1 * wv.z, s1 * wv.w));
    red_add_f32x4(&g_acc[(size_t)e2 * F + c],
                  make_float4(s2 * wv.x, s2 * wv.y, s2 * wv.z, s2 * wv.w));
}

// x_new = relu(acc + z[v] - z[u]); writes bf16 hi/lo splits (fp32 on last layer)
__global__ void fuse_relu_kernel(const int* __restrict__ edge_nodes, int write_f32) {
    int t = blockIdx.x * 256 + threadIdx.x;
    if (t >= NE * 64) return;
    int e = t >> 6, c = (t & 63) * 4;
    int u = edge_nodes[2 * e], v = edge_nodes[2 * e + 1];
    float4 a  = *(const float4*)&g_acc[(size_t)e * F + c];
    float4 zu = *(const float4*)&g_z[(size_t)u * F + c];
    float4 zv = *(const float4*)&g_z[(size_t)v * F + c];
    float4 r = make_float4(fmaxf(a.x + zv.x - zu.x, 0.f),
                           fmaxf(a.y + zv.y - zu.y, 0.f),
                           fmaxf(a.z + zv.z - zu.z, 0.f),
                           fmaxf(a.w + zv.w - zu.w, 0.f));
    size_t off = (size_t)e * F + c;
    if (write_f32) {
        *(float4*)&g_x[off] = r;
    } else {
        store_split4(off, r);
    }
}

__global__ void zero_out_kernel(float* out) {
    int i = blockIdx.x * 256 + threadIdx.x;
    if (i < NN) out[i] = 0.f;
}

__global__ void gemv_scatter_kernel(const float* __restrict__ WL,
                                    const int* __restrict__ edge_nodes,
                                    float* __restrict__ out) {
    __shared__ float ws[F];
    int tid = threadIdx.x;
    ws[tid] = WL[tid];
    __syncthreads();
    int warp = tid >> 5, lane = tid & 31;
    int e = blockIdx.x * 8 + warp;
    if (e >= NE) return;
    float s = 0.f;
#pragma unroll
    for (int j = 0; j < 8; j++) {
        int c = j * 32 + lane;
        s += g_x[(size_t)e * F + c] * ws[c];
    }
#pragma unroll
    for (int o = 16; o; o >>= 1) s += __shfl_xor_sync(0xffffffffu, s, o);
    if (lane == 0) {
        int u = edge_nodes[2 * e], v = edge_nodes[2 * e + 1];
        atomicAdd(&out[u], -s);
        atomicAdd(&out[v], s);
    }
}

// ---------------- launcher ------------------------------------------------------
extern "C" void kernel_launch(void* const* d_in, const int* in_sizes, int n_in,
                              void* d_out, int out_size) {
    const float* x        = (const float*)d_in[0];
    const float* W0s      = (const float*)d_in[1];
    const float* W1s      = (const float*)d_in[2];
    const float* W2s      = (const float*)d_in[3];
    const float* WL       = (const float*)d_in[4];
    const int* edge_nodes = (const int*)d_in[5];
    const int* tri_edges  = (const int*)d_in[6];
    const int* tri_signs  = (const int*)d_in[7];
    float* out            = (float*)d_out;

    cudaFuncSetAttribute(gemm_tc_kernel,
                         cudaFuncAttributeMaxDynamicSharedMemorySize, GSMEM_TOTAL);

    const int mtiles = (NE + 127) / 128;   // 1172

    convert_x_kernel<<<(NE * 64 + 255) / 256, 256>>>(x);
    convert_w_kernel<<<(NLAYERS * 3 * F * F + 255) / 256, 256>>>(W0s, W1s, W2s);

    for (int l = 0; l < NLAYERS; l++) {
        zero_z_kernel<<<(NN * F / 4 + 255) / 256, 256>>>();
        gemm_tc_kernel<<<dim3(mtiles, 6), 256, GSMEM_TOTAL>>>(l, edge_nodes);
        b2_fused_kernel<<<(NT * 64 + 255) / 256, 256>>>(tri_edges, tri_signs);
        fuse_relu_kernel<<<(NE * 64 + 255) / 256, 256>>>(edge_nodes,
                                                         (l == NLAYERS - 1) ? 1 : 0);
    }
    zero_out_kernel<<<(NN + 255) / 256, 256>>>(out);
    gemv_scatter_kernel<<<(NE + 7) / 8, 256>>>(WL, edge_nodes, out);
}

// round 12
// speedup vs baseline: 1.7986x; 1.0775x over previous
#include <cuda_runtime.h>
#include <cuda_bf16.h>
#include <cstdint>

#define NE 150000
#define NN 50000
#define NT 100000
#define F  256
#define NLAYERS 4

// ---------------- scratch (allocation-free: __device__ globals) ----------------
__device__ float g_y2[(size_t)NE * F];   // x @ W2
__device__ float g_acc[(size_t)NE * F];  // d1, then += d2 (atomics)
__device__ float g_x[(size_t)NE * F];    // final-layer x (fp32, for GEMV)
__device__ float g_z[(size_t)NN * F];    // node buffer for B1 (atomics)

// bf16 split operands for the tensor-core GEMM
__device__ __align__(16) __nv_bfloat16 g_x_hi[(size_t)NE * F];
__device__ __align__(16) __nv_bfloat16 g_x_lo[(size_t)NE * F];
__device__ __align__(16) __nv_bfloat16 g_wt_hi[NLAYERS * 3 * F * F]; // [l*3+mat][n][k]
__device__ __align__(16) __nv_bfloat16 g_wt_lo[NLAYERS * 3 * F * F];

// ---------------- PTX helpers (all sm_80-era, valid on sm_103 baseline) --------
__device__ __forceinline__ void red_add_f32x4(float* addr, float4 v) {
    asm volatile("red.global.add.v4.f32 [%0], {%1,%2,%3,%4};"
                 :: "l"(addr), "f"(v.x), "f"(v.y), "f"(v.z), "f"(v.w) : "memory");
}

__device__ __forceinline__ uint32_t smem_u32(const void* p) {
    uint32_t a;
    asm("{ .reg .u64 t; cvta.to.shared.u64 t, %1; cvt.u32.u64 %0, t; }"
        : "=r"(a) : "l"(p));
    return a;
}

__device__ __forceinline__ void cp16(uint32_t dst, const void* src, bool valid) {
    int sz = valid ? 16 : 0;
    asm volatile("cp.async.ca.shared.global [%0], [%1], 16, %2;"
                 :: "r"(dst), "l"(src), "r"(sz) : "memory");
}
__device__ __forceinline__ void cp_commit() {
    asm volatile("cp.async.commit_group;" ::: "memory");
}
__device__ __forceinline__ void cp_wait1() {
    asm volatile("cp.async.wait_group 1;" ::: "memory");
}

__device__ __forceinline__ void ldsm4(uint32_t& r0, uint32_t& r1, uint32_t& r2,
                                      uint32_t& r3, uint32_t addr) {
    asm volatile("ldmatrix.sync.aligned.m8n8.x4.shared.b16 {%0,%1,%2,%3}, [%4];"
                 : "=r"(r0), "=r"(r1), "=r"(r2), "=r"(r3) : "r"(addr));
}

__device__ __forceinline__ void mma_bf16(float* c, const uint32_t* a,
                                         uint32_t b0, uint32_t b1) {
    asm volatile(
        "mma.sync.aligned.m16n8k16.row.col.f32.bf16.bf16.f32 "
        "{%0,%1,%2,%3}, {%4,%5,%6,%7}, {%8,%9}, {%0,%1,%2,%3};"
        : "+f"(c[0]), "+f"(c[1]), "+f"(c[2]), "+f"(c[3])
        : "r"(a[0]), "r"(a[1]), "r"(a[2]), "r"(a[3]), "r"(b0), "r"(b1));
}

// ---------------- tensor-core GEMM: bf16x3 split, 3-stage cp.async -------------
// Block: 128(M) x 128(N), BK=32, 256 threads = 8 warps as 2(M) x 4(N).
// Smem row = [hi 64B | lo 64B] = 128B with SW128 xor swizzle.
// __launch_bounds__(256, 2): cap regs at 128 so 2 CTAs/SM co-reside
// (96KB smem x 2 = 192KB <= 228KB). Inner loop streams A frags per-mi to keep
// live registers ~100.
#define STAGE_BYTES 32768   /* A 16KB + B 16KB */
#define GSMEM_TOTAL (3 * STAGE_BYTES)

__global__ __launch_bounds__(256, 2) void gemm_tc_kernel(
    int layer, const int* __restrict__ edge_nodes)
{
    extern __shared__ char smem[];
    const uint32_t smem_base = smem_u32(smem);

    const int tid  = threadIdx.x;
    const int lane = tid & 31;
    const int w    = tid >> 5;
    const int wm   = w & 1;          // 0..1 -> 64 M-rows each
    const int wn   = w >> 1;         // 0..3 -> 32 N-cols each

    const int mat = blockIdx.y >> 1;
    const int n0  = (blockIdx.y & 1) * 128;
    const int m0  = blockIdx.x * 128;

    const size_t wofs = (size_t)(layer * 3 + mat) * 65536 + (size_t)n0 * 256;
    const __nv_bfloat16* Bh = g_wt_hi + wofs;
    const __nv_bfloat16* Bl = g_wt_lo + wofs;

    // ldmatrix lane address decomposition (same pattern for A and B)
    const int g     = lane >> 3;                       // 0..3
    const int rlane = (lane & 7) + ((g & 1) << 3);     // row-in-frag 0..15
    const int khalf = g >> 1;                          // 0..1 (k 16B chunk)

    float acc[4][4][4];
#pragma unroll
    for (int mi = 0; mi < 4; mi++)
#pragma unroll
        for (int nj = 0; nj < 4; nj++)
#pragma unroll
            for (int r = 0; r < 4; r++) acc[mi][nj][r] = 0.f;

    // ---- tile loader: stage s, K-chunk kc (kc in 0..7, 32 cols each) ----
    auto load_tiles = [&](int s, int kc) {
        uint32_t sA = smem_base + s * STAGE_BYTES;
        uint32_t sB = sA + 16384;
#pragma unroll
        for (int i = 0; i < 4; i++) {               // A: 1024 16B chunks
            int ch  = tid + i * 256;
            int row = ch >> 3, pos = ch & 7;        // pos 0-3 hi, 4-7 lo
            int split = pos >> 2, p4 = pos & 3;
            int grow = m0 + row;
            bool v = (grow < NE);
            int r = v ? grow : 0;
            const __nv_bfloat16* src =
                (split ? g_x_lo : g_x_hi) + (size_t)r * F + kc * 32 + p4 * 8;
            uint32_t dst = sA + row * 128 + ((pos ^ (row & 7)) << 4);
            cp16(dst, src, v);
        }
#pragma unroll
        for (int i = 0; i < 4; i++) {               // B: 1024 16B chunks
            int ch  = tid + i * 256;
            int row = ch >> 3, pos = ch & 7;
            int split = pos >> 2, p4 = pos & 3;
            const __nv_bfloat16* src =
                (split ? Bl : Bh) + (size_t)row * 256 + kc * 32 + p4 * 8;
            uint32_t dst = sB + row * 128 + ((pos ^ (row & 7)) << 4);
            cp16(dst, src, true);
        }
    };

    load_tiles(0, 0); cp_commit();
    load_tiles(1, 1); cp_commit();

    for (int kc = 0; kc < 8; kc++) {
        cp_wait1();
        __syncthreads();

        // prefetch kc+2 into the stage consumed last iteration
        if (kc + 2 < 8) load_tiles((kc + 2) % 3, kc + 2);
        cp_commit();

        const int st = kc % 3;
        uint32_t sA = smem_base + st * STAGE_BYTES;
        uint32_t sB = sA + 16384;

#pragma unroll
        for (int ks = 0; ks < 2; ks++) {
            const int chH = ks * 2 + khalf;        // hi chunk idx 0..3
            const int chL = chH + 4;               // lo chunk idx 4..7

            // B fragments for this ks: 16 regs, live across the mi loop
            uint32_t bh[2][4], bl[2][4];
#pragma unroll
            for (int j = 0; j < 2; j++) {
                int row = wn * 32 + j * 16 + rlane;
                uint32_t base = sB + row * 128;
                ldsm4(bh[j][0], bh[j][1], bh[j][2], bh[j][3],
                      base + ((chH ^ (row & 7)) << 4));
                ldsm4(bl[j][0], bl[j][1], bl[j][2], bl[j][3],
                      base + ((chL ^ (row & 7)) << 4));
            }

            // stream A fragments per mi: only 8 A regs live at a time
#pragma unroll
            for (int mi = 0; mi < 4; mi++) {
                int row = wm * 64 + mi * 16 + rlane;
                uint32_t base = sA + row * 128;
                uint32_t ah[4], al[4];
                ldsm4(ah[0], ah[1], ah[2], ah[3],
                      base + ((chH ^ (row & 7)) << 4));
                ldsm4(al[0], al[1], al[2], al[3],
                      base + ((chL ^ (row & 7)) << 4));
#pragma unroll
                for (int nj = 0; nj < 4; nj++) {
                    int j = nj >> 1, o = nj & 1;
                    mma_bf16(acc[mi][nj], ah, bh[j][o], bh[j][o + 2]); // hi*hi
                    mma_bf16(acc[mi][nj], ah, bl[j][o], bl[j][o + 2]); // hi*lo
                    mma_bf16(acc[mi][nj], al, bh[j][o], bh[j][o + 2]); // lo*hi
                }
            }
        }
        __syncthreads();
    }

    const int crow = lane >> 2;
    const int ccol = (lane & 3) * 2;

    if (mat == 0) {
        // ---- fused B1 scatter: z[u] -= y0, z[v] += y0 (red.v4 via lane pair) --
#pragma unroll
        for (int mi = 0; mi < 4; mi++) {
            int r0 = m0 + wm * 64 + mi * 16 + crow;
            int r1 = r0 + 8;
            int u0 = 0, v0 = 0, u1 = 0, v1 = 0;
            if (r0 < NE) { u0 = edge_nodes[2 * r0]; v0 = edge_nodes[2 * r0 + 1]; }
            if (r1 < NE) { u1 = edge_nodes[2 * r1]; v1 = edge_nodes[2 * r1 + 1]; }
            int gc = n0 + wn * 32 + (lane & 2) * 2;  // float4 col base (per pair)
#pragma unroll
            for (int nj = 0; nj < 4; nj++) {
                float x0 = acc[mi][nj][0], y0 = acc[mi][nj][1];
                float x1 = acc[mi][nj][2], y1 = acc[mi][nj][3];
                float px0 = __shfl_xor_sync(0xffffffffu, x0, 1);
                float py0 = __shfl_xor_sync(0xffffffffu, y0, 1);
                float px1 = __shfl_xor_sync(0xffffffffu, x1, 1);
                float py1 = __shfl_xor_sync(0xffffffffu, y1, 1);
                if (!(lane & 1)) {
                    int c = gc + nj * 8;
                    if (r0 < NE) {
                        float4 q = make_float4(x0, y0, px0, py0);
                        red_add_f32x4(&g_z[(size_t)u0 * F + c],
                                      make_float4(-q.x, -q.y, -q.z, -q.w));
                        red_add_f32x4(&g_z[(size_t)v0 * F + c], q);
                    }
                    if (r1 < NE) {
                        float4 q = make_float4(x1, y1, px1, py1);
                        red_add_f32x4(&g_z[(size_t)u1 * F + c],
                                      make_float4(-q.x, -q.y, -q.z, -q.w));
                        red_add_f32x4(&g_z[(size_t)v1 * F + c], q);
                    }
                }
            }
        }
    } else {
        float* OUT = (mat == 1) ? g_acc : g_y2;
#pragma unroll
        for (int mi = 0; mi < 4; mi++) {
#pragma unroll
            for (int nj = 0; nj < 4; nj++) {
                int gr = m0 + wm * 64 + mi * 16 + crow;
                int gc = n0 + wn * 32 + nj * 8 + ccol;
                if (gr < NE)
                    *(float2*)&OUT[(size_t)gr * F + gc] =
                        make_float2(acc[mi][nj][0], acc[mi][nj][1]);
                if (gr + 8 < NE)
                    *(float2*)&OUT[(size_t)(gr + 8) * F + gc] =
                        make_float2(acc[mi][nj][2], acc[mi][nj][3]);
            }
        }
    }
}

// ---------------- bf16 split conversion ----------------------------------------
__device__ __forceinline__ void split2(float v, unsigned short& h, unsigned short& l) {
    __nv_bfloat16 hb = __float2bfloat16(v);
    float hf = __bfloat162float(hb);
    __nv_bfloat16 lb = __float2bfloat16(v - hf);
    h = reinterpret_cast<unsigned short&>(hb);
    l = reinterpret_cast<unsigned short&>(lb);
}

__device__ __forceinline__ void store_split4(size_t off, float4 r) {
    unsigned short h[4], l[4];
    split2(r.x, h[0], l[0]); split2(r.y, h[1], l[1]);
    split2(r.z, h[2], l[2]); split2(r.w, h[3], l[3]);
    uint2 H = make_uint2((uint32_t)h[0] | ((uint32_t)h[1] << 16),
                         (uint32_t)h[2] | ((uint32_t)h[3] << 16));
    uint2 L = make_uint2((uint32_t)l[0] | ((uint32_t)l[1] << 16),
                         (uint32_t)l[2] | ((uint32_t)l[3] << 16));
    *(uint2*)&g_x_hi[off] = H;
    *(uint2*)&g_x_lo[off] = L;
}

__global__ void convert_x_kernel(const float* __restrict__ x) {
    int t = blockIdx.x * 256 + threadIdx.x;
    if (t >= NE * 64) return;
    int e = t >> 6, c = (t & 63) * 4;
    float4 v = *(const float4*)&x[(size_t)e * F + c];
    store_split4((size_t)e * F + c, v);
}

// all layers at once: g_wt_{hi,lo}[l*3+mat][n][k] = split(W_mat^l[k][n])
__global__ void convert_w_kernel(const float* __restrict__ W0,
                                 const float* __restrict__ W1,
                                 const float* __restrict__ W2) {
    int t = blockIdx.x * 256 + threadIdx.x;
    if (t >= NLAYERS * 3 * F * F) return;
    int lm = t >> 16, r = t & 65535, n = r >> 8, k = r & 255;
    int l = lm / 3, mat = lm % 3;
    const float* W = ((mat == 0) ? W0 : (mat == 1) ? W1 : W2) + (size_t)l * F * F;
    float v = W[k * F + n];
    unsigned short h, lo;
    split2(v, h, lo);
    g_wt_hi[t] = reinterpret_cast<__nv_bfloat16&>(h);
    g_wt_lo[t] = reinterpret_cast<__nv_bfloat16&>(lo);
}

// ---------------- graph ops ----------------------------------------------------
__global__ void zero_z_kernel() {
    int i = blockIdx.x * 256 + threadIdx.x;
    if (i < NN * F / 4) ((float4*)g_z)[i] = make_float4(0.f, 0.f, 0.f, 0.f);
}

// fused B2: w = sum_k s_k * y2[e_k]; acc[e_k] += s_k * w   (no g_w round trip)
__global__ void b2_fused_kernel(const int* __restrict__ tri_edges,
                                const int* __restrict__ tri_signs) {
    int t = blockIdx.x * 256 + threadIdx.x;
    if (t >= NT * 64) return;
    int tri = t >> 6, c = (t & 63) * 4;
    int e0 = tri_edges[3 * tri], e1 = tri_edges[3 * tri + 1], e2 = tri_edges[3 * tri + 2];
    float s0 = (float)tri_signs[3 * tri];
    float s1 = (float)tri_signs[3 * tri + 1];
    float s2 = (float)tri_signs[3 * tri + 2];
    float4 v0 = *(const float4*)&g_y2[(size_t)e0 * F + c];
    float4 v1 = *(const float4*)&g_y2[(size_t)e1 * F + c];
    float4 v2 = *(const float4*)&g_y2[(size_t)e2 * F + c];
    float4 wv = make_float4(s0 * v0.x + s1 * v1.x + s2 * v2.x,
                            s0 * v0.y + s1 * v1.y + s2 * v2.y,
                            s0 * v0.z + s1 * v1.z + s2 * v2.z,
                            s0 * v0.w + s1 * v1.w + s2 * v2.w);
    red_add_f32x4(&g_acc[(size_t)e0 * F + c],
                  make_float4(s0 * wv.x, s0 * wv.y, s0 * wv.z, s0 * wv.w));
    red_add_f32x4(&g_acc[(size_t)e1 * F + c],
                  make_float4(s1 * wv.x, s1 * wv.y, s1 * wv.z, s1 * wv.w));
    red_add_f32x4(&g_acc[(size_t)e2 * F + c],
                  make_float4(s2 * wv.x, s2 * wv.y, s2 * wv.z, s2 * wv.w));
}

// x_new = relu(acc + z[v] - z[u]); writes bf16 hi/lo splits (fp32 on last layer)
__global__ void fuse_relu_kernel(const int* __restrict__ edge_nodes, int write_f32) {
    int t = blockIdx.x * 256 + threadIdx.x;
    if (t >= NE * 64) return;
    int e = t >> 6, c = (t & 63) * 4;
    int u = edge_nodes[2 * e], v = edge_nodes[2 * e + 1];
    float4 a  = *(const float4*)&g_acc[(size_t)e * F + c];
    float4 zu = *(const float4*)&g_z[(size_t)u * F + c];
    float4 zv = *(const float4*)&g_z[(size_t)v * F + c];
    float4 r = make_float4(fmaxf(a.x + zv.x - zu.x, 0.f),
                           fmaxf(a.y + zv.y - zu.y, 0.f),
                           fmaxf(a.z + zv.z - zu.z, 0.f),
                           fmaxf(a.w + zv.w - zu.w, 0.f));
    size_t off = (size_t)e * F + c;
    if (write_f32) {
        *(float4*)&g_x[off] = r;
    } else {
        store_split4(off, r);
    }
}

__global__ void zero_out_kernel(float* out) {
    int i = blockIdx.x * 256 + threadIdx.x;
    if (i < NN) out[i] = 0.f;
}

__global__ void gemv_scatter_kernel(const float* __restrict__ WL,
                                    const int* __restrict__ edge_nodes,
                                    float* __restrict__ out) {
    __shared__ float ws[F];
    int tid = threadIdx.x;
    ws[tid] = WL[tid];
    __syncthreads();
    int warp = tid >> 5, lane = tid & 31;
    int e = blockIdx.x * 8 + warp;
    if (e >= NE) return;
    float s = 0.f;
#pragma unroll
    for (int j = 0; j < 8; j++) {
        int c = j * 32 + lane;
        s += g_x[(size_t)e * F + c] * ws[c];
    }
#pragma unroll
    for (int o = 16; o; o >>= 1) s += __shfl_xor_sync(0xffffffffu, s, o);
    if (lane == 0) {
        int u = edge_nodes[2 * e], v = edge_nodes[2 * e + 1];
        atomicAdd(&out[u], -s);
        atomicAdd(&out[v], s);
    }
}

// ---------------- launcher ------------------------------------------------------
extern "C" void kernel_launch(void* const* d_in, const int* in_sizes, int n_in,
                              void* d_out, int out_size) {
    const float* x        = (const float*)d_in[0];
    const float* W0s      = (const float*)d_in[1];
    const float* W1s      = (const float*)d_in[2];
    const float* W2s      = (const float*)d_in[3];
    const float* WL       = (const float*)d_in[4];
    const int* edge_nodes = (const int*)d_in[5];
    const int* tri_edges  = (const int*)d_in[6];
    const int* tri_signs  = (const int*)d_in[7];
    float* out            = (float*)d_out;

    cudaFuncSetAttribute(gemm_tc_kernel,
                         cudaFuncAttributeMaxDynamicSharedMemorySize, GSMEM_TOTAL);

    const int mtiles = (NE + 127) / 128;   // 1172

    convert_x_kernel<<<(NE * 64 + 255) / 256, 256>>>(x);
    convert_w_kernel<<<(NLAYERS * 3 * F * F + 255) / 256, 256>>>(W0s, W1s, W2s);

    for (int l = 0; l < NLAYERS; l++) {
        zero_z_kernel<<<(NN * F / 4 + 255) / 256, 256>>>();
        gemm_tc_kernel<<<dim3(mtiles, 6), 256, GSMEM_TOTAL>>>(l, edge_nodes);
        b2_fused_kernel<<<(NT * 64 + 255) / 256, 256>>>(tri_edges, tri_signs);
        fuse_relu_kernel<<<(NE * 64 + 255) / 256, 256>>>(edge_nodes,
                                                         (l == NLAYERS - 1) ? 1 : 0);
    }
    zero_out_kernel<<<(NN + 255) / 256, 256>>>(out);
    gemv_scatter_kernel<<<(NE + 7) / 8, 256>>>(WL, edge_nodes, out);
}

// round 13
// speedup vs baseline: 2.2836x; 1.2697x over previous
#include <cuda_runtime.h>
#include <cuda_fp16.h>
#include <cstdint>

#define NE 150000
#define NN 50000
#define NT 100000
#define F  256
#define NLAYERS 4

// ---------------- scratch (allocation-free: __device__ globals) ----------------
__device__ float g_y2[(size_t)NE * F];   // x @ W2
__device__ float g_acc[(size_t)NE * F];  // d1, then += d2 (atomics)
__device__ float g_x[(size_t)NE * F];    // final-layer x (fp32, for GEMV)
__device__ float g_z[(size_t)NN * F];    // node buffer for B1 (atomics)

// fp16 split operands: activations hi+lo (22 bits), weights single fp16
__device__ __align__(16) __half g_x_hi[(size_t)NE * F];
__device__ __align__(16) __half g_x_lo[(size_t)NE * F];
__device__ __align__(16) __half g_wt[NLAYERS * 3 * F * F];   // [l*3+mat][n][k]

// ---------------- PTX helpers (all sm_80-era, valid on sm_103 baseline) --------
__device__ __forceinline__ void red_add_f32x4(float* addr, float4 v) {
    asm volatile("red.global.add.v4.f32 [%0], {%1,%2,%3,%4};"
                 :: "l"(addr), "f"(v.x), "f"(v.y), "f"(v.z), "f"(v.w) : "memory");
}

__device__ __forceinline__ uint32_t smem_u32(const void* p) {
    uint32_t a;
    asm("{ .reg .u64 t; cvta.to.shared.u64 t, %1; cvt.u32.u64 %0, t; }"
        : "=r"(a) : "l"(p));
    return a;
}

__device__ __forceinline__ void cp16(uint32_t dst, const void* src, bool valid) {
    int sz = valid ? 16 : 0;
    asm volatile("cp.async.ca.shared.global [%0], [%1], 16, %2;"
                 :: "r"(dst), "l"(src), "r"(sz) : "memory");
}
__device__ __forceinline__ void cp_commit() {
    asm volatile("cp.async.commit_group;" ::: "memory");
}
__device__ __forceinline__ void cp_wait2() {
    asm volatile("cp.async.wait_group 2;" ::: "memory");
}

__device__ __forceinline__ void ldsm4(uint32_t& r0, uint32_t& r1, uint32_t& r2,
                                      uint32_t& r3, uint32_t addr) {
    asm volatile("ldmatrix.sync.aligned.m8n8.x4.shared.b16 {%0,%1,%2,%3}, [%4];"
                 : "=r"(r0), "=r"(r1), "=r"(r2), "=r"(r3) : "r"(addr));
}

__device__ __forceinline__ void mma_f16(float* c, const uint32_t* a,
                                        uint32_t b0, uint32_t b1) {
    asm volatile(
        "mma.sync.aligned.m16n8k16.row.col.f32.f16.f16.f32 "
        "{%0,%1,%2,%3}, {%4,%5,%6,%7}, {%8,%9}, {%0,%1,%2,%3};"
        : "+f"(c[0]), "+f"(c[1]), "+f"(c[2]), "+f"(c[3])
        : "r"(a[0]), "r"(a[1]), "r"(a[2]), "r"(a[3]), "r"(b0), "r"(b1));
}

// ---------------- tensor-core GEMM: fp16 hi/lo x W(fp16), 2 MMA products ------
// Block: 128(M) x 128(N), BK=32, 256 threads = 8 warps as 2(M) x 4(N).
// A smem row = [hi 64B | lo 64B] = 128B, SW128 xor swizzle.
// B smem row = 64B (single fp16), 64B xor swizzle.
// 4-stage cp.async pipeline; 2 CTAs/SM (96KB smem, 128 regs).
#define STAGE_BYTES 24576   /* A 16KB + B 8KB */
#define GSMEM_TOTAL (4 * STAGE_BYTES)

__global__ __launch_bounds__(256, 2) void gemm_tc_kernel(
    int layer, const int* __restrict__ edge_nodes)
{
    extern __shared__ char smem[];
    const uint32_t smem_base = smem_u32(smem);

    const int tid  = threadIdx.x;
    const int lane = tid & 31;
    const int w    = tid >> 5;
    const int wm   = w & 1;          // 0..1 -> 64 M-rows each
    const int wn   = w >> 1;         // 0..3 -> 32 N-cols each

    const int mat = blockIdx.y >> 1;
    const int n0  = (blockIdx.y & 1) * 128;
    const int m0  = blockIdx.x * 128;

    const __half* Wt = g_wt + (size_t)(layer * 3 + mat) * 65536 + (size_t)n0 * 256;

    // ldmatrix lane address decomposition (same pattern for A and B)
    const int g     = lane >> 3;                       // 0..3
    const int rlane = (lane & 7) + ((g & 1) << 3);     // row-in-frag 0..15
    const int khalf = g >> 1;                          // 0..1 (k 16B chunk)

    float acc[4][4][4];
#pragma unroll
    for (int mi = 0; mi < 4; mi++)
#pragma unroll
        for (int nj = 0; nj < 4; nj++)
#pragma unroll
            for (int r = 0; r < 4; r++) acc[mi][nj][r] = 0.f;

    // ---- tile loader: stage s, K-chunk kc (kc in 0..7, 32 cols each) ----
    auto load_tiles = [&](int s, int kc) {
        uint32_t sA = smem_base + s * STAGE_BYTES;
        uint32_t sB = sA + 16384;
#pragma unroll
        for (int i = 0; i < 4; i++) {               // A: 1024 16B chunks
            int ch  = tid + i * 256;
            int row = ch >> 3, pos = ch & 7;        // pos 0-3 hi, 4-7 lo
            int split = pos >> 2, p4 = pos & 3;
            int grow = m0 + row;
            bool v = (grow < NE);
            int r = v ? grow : 0;
            const __half* src =
                (split ? g_x_lo : g_x_hi) + (size_t)r * F + kc * 32 + p4 * 8;
            uint32_t dst = sA + row * 128 + ((pos ^ (row & 7)) << 4);
            cp16(dst, src, v);
        }
#pragma unroll
        for (int i = 0; i < 2; i++) {               // B: 512 16B chunks
            int ch  = tid + i * 256;
            int row = ch >> 2, pos = ch & 3;        // 64B rows
            const __half* src = Wt + (size_t)row * 256 + kc * 32 + pos * 8;
            uint32_t dst = sB + row * 64 + ((pos ^ ((row >> 1) & 3)) << 4);
            cp16(dst, src, true);
        }
    };

    load_tiles(0, 0); cp_commit();
    load_tiles(1, 1); cp_commit();
    load_tiles(2, 2); cp_commit();

    for (int kc = 0; kc < 8; kc++) {
        cp_wait2();
        __syncthreads();

        // prefetch kc+3 into the stage consumed in the previous iteration
        if (kc + 3 < 8) load_tiles((kc + 3) & 3, kc + 3);
        cp_commit();

        const int st = kc & 3;
        uint32_t sA = smem_base + st * STAGE_BYTES;
        uint32_t sB = sA + 16384;

#pragma unroll
        for (int ks = 0; ks < 2; ks++) {
            const int cH = ks * 2 + khalf;         // 16B k-chunk idx 0..3

            // B fragments for this ks: 8 regs, live across the mi loop
            uint32_t bh[2][4];
#pragma unroll
            for (int j = 0; j < 2; j++) {
                int row = wn * 32 + j * 16 + rlane;
                ldsm4(bh[j][0], bh[j][1], bh[j][2], bh[j][3],
                      sB + row * 64 + ((cH ^ ((row >> 1) & 3)) << 4));
            }

            // stream A fragments per mi: 8 A regs live at a time
#pragma unroll
            for (int mi = 0; mi < 4; mi++) {
                int row = wm * 64 + mi * 16 + rlane;
                uint32_t base = sA + row * 128;
                uint32_t ah[4], al[4];
                ldsm4(ah[0], ah[1], ah[2], ah[3],
                      base + ((cH ^ (row & 7)) << 4));
                ldsm4(al[0], al[1], al[2], al[3],
                      base + (((cH + 4) ^ (row & 7)) << 4));
#pragma unroll
                for (int nj = 0; nj < 4; nj++) {
                    int j = nj >> 1, o = nj & 1;
                    mma_f16(acc[mi][nj], ah, bh[j][o], bh[j][o + 2]); // hi * w
                    mma_f16(acc[mi][nj], al, bh[j][o], bh[j][o + 2]); // lo * w
                }
            }
        }
        __syncthreads();
    }

    const int crow = lane >> 2;
    const int ccol = (lane & 3) * 2;

    if (mat == 0) {
        // ---- fused B1 scatter: z[u] -= y0, z[v] += y0 (red.v4 via lane pair) --
#pragma unroll
        for (int mi = 0; mi < 4; mi++) {
            int r0 = m0 + wm * 64 + mi * 16 + crow;
            int r1 = r0 + 8;
            int u0 = 0, v0 = 0, u1 = 0, v1 = 0;
            if (r0 < NE) { u0 = edge_nodes[2 * r0]; v0 = edge_nodes[2 * r0 + 1]; }
            if (r1 < NE) { u1 = edge_nodes[2 * r1]; v1 = edge_nodes[2 * r1 + 1]; }
            int gc = n0 + wn * 32 + (lane & 2) * 2;  // float4 col base (per pair)
#pragma unroll
            for (int nj = 0; nj < 4; nj++) {
                float x0 = acc[mi][nj][0], y0 = acc[mi][nj][1];
                float x1 = acc[mi][nj][2], y1 = acc[mi][nj][3];
                float px0 = __shfl_xor_sync(0xffffffffu, x0, 1);
                float py0 = __shfl_xor_sync(0xffffffffu, y0, 1);
                float px1 = __shfl_xor_sync(0xffffffffu, x1, 1);
                float py1 = __shfl_xor_sync(0xffffffffu, y1, 1);
                if (!(lane & 1)) {
                    int c = gc + nj * 8;
                    if (r0 < NE) {
                        float4 q = make_float4(x0, y0, px0, py0);
                        red_add_f32x4(&g_z[(size_t)u0 * F + c],
                                      make_float4(-q.x, -q.y, -q.z, -q.w));
                        red_add_f32x4(&g_z[(size_t)v0 * F + c], q);
                    }
                    if (r1 < NE) {
                        float4 q = make_float4(x1, y1, px1, py1);
                        red_add_f32x4(&g_z[(size_t)u1 * F + c],
                                      make_float4(-q.x, -q.y, -q.z, -q.w));
                        red_add_f32x4(&g_z[(size_t)v1 * F + c], q);
                    }
                }
            }
        }
    } else {
        float* OUT = (mat == 1) ? g_acc : g_y2;
#pragma unroll
        for (int mi = 0; mi < 4; mi++) {
#pragma unroll
            for (int nj = 0; nj < 4; nj++) {
                int gr = m0 + wm * 64 + mi * 16 + crow;
                int gc = n0 + wn * 32 + nj * 8 + ccol;
                if (gr < NE)
                    *(float2*)&OUT[(size_t)gr * F + gc] =
                        make_float2(acc[mi][nj][0], acc[mi][nj][1]);
                if (gr + 8 < NE)
                    *(float2*)&OUT[(size_t)(gr + 8) * F + gc] =
                        make_float2(acc[mi][nj][2], acc[mi][nj][3]);
            }
        }
    }
}

// ---------------- fp16 split conversion -----------------------------------------
__device__ __forceinline__ void split2h(float v, __half& h, __half& l) {
    h = __float2half_rn(v);
    l = __float2half_rn(v - __half2float(h));
}

__device__ __forceinline__ void store_split4(size_t off, float4 r) {
    __half h[4], l[4];
    split2h(r.x, h[0], l[0]); split2h(r.y, h[1], l[1]);
    split2h(r.z, h[2], l[2]); split2h(r.w, h[3], l[3]);
    *(uint2*)&g_x_hi[off] = *(uint2*)h;
    *(uint2*)&g_x_lo[off] = *(uint2*)l;
}

__global__ void convert_x_kernel(const float* __restrict__ x) {
    int t = blockIdx.x * 256 + threadIdx.x;
    if (t >= NE * 64) return;
    int e = t >> 6, c = (t & 63) * 4;
    float4 v = *(const float4*)&x[(size_t)e * F + c];
    store_split4((size_t)e * F + c, v);
}

// all layers at once: g_wt[l*3+mat][n][k] = fp16(W_mat^l[k][n])
__global__ void convert_w_kernel(const float* __restrict__ W0,
                                 const float* __restrict__ W1,
                                 const float* __restrict__ W2) {
    int t = blockIdx.x * 256 + threadIdx.x;
    if (t >= NLAYERS * 3 * F * F) return;
    int lm = t >> 16, r = t & 65535, n = r >> 8, k = r & 255;
    int l = lm / 3, mat = lm % 3;
    const float* W = ((mat == 0) ? W0 : (mat == 1) ? W1 : W2) + (size_t)l * F * F;
    g_wt[t] = __float2half_rn(W[k * F + n]);
}

// ---------------- graph ops ----------------------------------------------------
__global__ void zero_z_kernel() {
    int i = blockIdx.x * 256 + threadIdx.x;
    if (i < NN * F / 4) ((float4*)g_z)[i] = make_float4(0.f, 0.f, 0.f, 0.f);
}

// fused B2: w = sum_k s_k * y2[e_k]; acc[e_k] += s_k * w   (no round trip)
__global__ void b2_fused_kernel(const int* __restrict__ tri_edges,
                                const int* __restrict__ tri_signs) {
    int t = blockIdx.x * 256 + threadIdx.x;
    if (t >= NT * 64) return;
    int tri = t >> 6, c = (t & 63) * 4;
    int e0 = tri_edges[3 * tri], e1 = tri_edges[3 * tri + 1], e2 = tri_edges[3 * tri + 2];
    float s0 = (float)tri_signs[3 * tri];
    float s1 = (float)tri_signs[3 * tri + 1];
    float s2 = (float)tri_signs[3 * tri + 2];
    float4 v0 = *(const float4*)&g_y2[(size_t)e0 * F + c];
    float4 v1 = *(const float4*)&g_y2[(size_t)e1 * F + c];
    float4 v2 = *(const float4*)&g_y2[(size_t)e2 * F + c];
    float4 wv = make_float4(s0 * v0.x + s1 * v1.x + s2 * v2.x,
                            s0 * v0.y + s1 * v1.y + s2 * v2.y,
                            s0 * v0.z + s1 * v1.z + s2 * v2.z,
                            s0 * v0.w + s1 * v1.w + s2 * v2.w);
    red_add_f32x4(&g_acc[(size_t)e0 * F + c],
                  make_float4(s0 * wv.x, s0 * wv.y, s0 * wv.z, s0 * wv.w));
    red_add_f32x4(&g_acc[(size_t)e1 * F + c],
                  make_float4(s1 * wv.x, s1 * wv.y, s1 * wv.z, s1 * wv.w));
    red_add_f32x4(&g_acc[(size_t)e2 * F + c],
                  make_float4(s2 * wv.x, s2 * wv.y, s2 * wv.z, s2 * wv.w));
}

// x_new = relu(acc + z[v] - z[u]); writes fp16 hi/lo splits (fp32 on last layer)
__global__ void fuse_relu_kernel(const int* __restrict__ edge_nodes, int write_f32) {
    int t = blockIdx.x * 256 + threadIdx.x;
    if (t >= NE * 64) return;
    int e = t >> 6, c = (t & 63) * 4;
    int u = edge_nodes[2 * e], v = edge_nodes[2 * e + 1];
    float4 a  = *(const float4*)&g_acc[(size_t)e * F + c];
    float4 zu = *(const float4*)&g_z[(size_t)u * F + c];
    float4 zv = *(const float4*)&g_z[(size_t)v * F + c];
    float4 r = make_float4(fmaxf(a.x + zv.x - zu.x, 0.f),
                           fmaxf(a.y + zv.y - zu.y, 0.f),
                           fmaxf(a.z + zv.z - zu.z, 0.f),
                           fmaxf(a.w + zv.w - zu.w, 0.f));
    size_t off = (size_t)e * F + c;
    if (write_f32) {
        *(float4*)&g_x[off] = r;
    } else {
        store_split4(off, r);
    }
}

__global__ void zero_out_kernel(float* out) {
    int i = blockIdx.x * 256 + threadIdx.x;
    if (i < NN) out[i] = 0.f;
}

__global__ void gemv_scatter_kernel(const float* __restrict__ WL,
                                    const int* __restrict__ edge_nodes,
                                    float* __restrict__ out) {
    __shared__ float ws[F];
    int tid = threadIdx.x;
    ws[tid] = WL[tid];
    __syncthreads();
    int warp = tid >> 5, lane = tid & 31;
    int e = blockIdx.x * 8 + warp;
    if (e >= NE) return;
    float s = 0.f;
#pragma unroll
    for (int j = 0; j < 8; j++) {
        int c = j * 32 + lane;
        s += g_x[(size_t)e * F + c] * ws[c];
    }
#pragma unroll
    for (int o = 16; o; o >>= 1) s += __shfl_xor_sync(0xffffffffu, s, o);
    if (lane == 0) {
        int u = edge_nodes[2 * e], v = edge_nodes[2 * e + 1];
        atomicAdd(&out[u], -s);
        atomicAdd(&out[v], s);
    }
}

// ---------------- launcher ------------------------------------------------------
extern "C" void kernel_launch(void* const* d_in, const int* in_sizes, int n_in,
                              void* d_out, int out_size) {
    const float* x        = (const float*)d_in[0];
    const float* W0s      = (const float*)d_in[1];
    const float* W1s      = (const float*)d_in[2];
    const float* W2s      = (const float*)d_in[3];
    const float* WL       = (const float*)d_in[4];
    const int* edge_nodes = (const int*)d_in[5];
    const int* tri_edges  = (const int*)d_in[6];
    const int* tri_signs  = (const int*)d_in[7];
    float* out            = (float*)d_out;

    cudaFuncSetAttribute(gemm_tc_kernel,
                         cudaFuncAttributeMaxDynamicSharedMemorySize, GSMEM_TOTAL);

    const int mtiles = (NE + 127) / 128;   // 1172

    convert_x_kernel<<<(NE * 64 + 255) / 256, 256>>>(x);
    convert_w_kernel<<<(NLAYERS * 3 * F * F + 255) / 256, 256>>>(W0s, W1s, W2s);

    for (int l = 0; l < NLAYERS; l++) {
        zero_z_kernel<<<(NN * F / 4 + 255) / 256, 256>>>();
        gemm_tc_kernel<<<dim3(mtiles, 6), 256, GSMEM_TOTAL>>>(l, edge_nodes);
        b2_fused_kernel<<<(NT * 64 + 255) / 256, 256>>>(tri_edges, tri_signs);
        fuse_relu_kernel<<<(NE * 64 + 255) / 256, 256>>>(edge_nodes,
                                                         (l == NLAYERS - 1) ? 1 : 0);
    }
    zero_out_kernel<<<(NN + 255) / 256, 256>>>(out);
    gemv_scatter_kernel<<<(NE + 7) / 8, 256>>>(WL, edge_nodes, out);
}

// round 14
// speedup vs baseline: 2.3417x; 1.0255x over previous
#include <cuda_runtime.h>
#include <cuda_fp16.h>
#include <cstdint>

#define NE 150000
#define NN 50000
#define NT 100000
#define F  256
#define NLAYERS 4

// ---------------- scratch (allocation-free: __device__ globals) ----------------
__device__ float g_y2[(size_t)NE * F];   // x @ W2
__device__ float g_acc[(size_t)NE * F];  // d1, then += d2 (atomics)
__device__ float g_x[(size_t)NE * F];    // final-layer x (fp32, for GEMV)
__device__ float g_z[(size_t)NN * F];    // node buffer for B1 (atomics)

// fp16 split operands: activations hi+lo (22 bits), weights single fp16
__device__ __align__(16) __half g_x_hi[(size_t)NE * F];
__device__ __align__(16) __half g_x_lo[(size_t)NE * F];
__device__ __align__(16) __half g_wt[NLAYERS * 3 * F * F];   // [l*3+mat][n][k]

// ---------------- PTX helpers (all sm_80-era, valid on sm_103 baseline) --------
__device__ __forceinline__ void red_add_f32x4(float* addr, float4 v) {
    asm volatile("red.global.add.v4.f32 [%0], {%1,%2,%3,%4};"
                 :: "l"(addr), "f"(v.x), "f"(v.y), "f"(v.z), "f"(v.w) : "memory");
}

__device__ __forceinline__ uint32_t smem_u32(const void* p) {
    uint32_t a;
    asm("{ .reg .u64 t; cvta.to.shared.u64 t, %1; cvt.u32.u64 %0, t; }"
        : "=r"(a) : "l"(p));
    return a;
}

__device__ __forceinline__ void cp16(uint32_t dst, const void* src, bool valid) {
    int sz = valid ? 16 : 0;
    asm volatile("cp.async.ca.shared.global [%0], [%1], 16, %2;"
                 :: "r"(dst), "l"(src), "r"(sz) : "memory");
}
__device__ __forceinline__ void cp_commit() {
    asm volatile("cp.async.commit_group;" ::: "memory");
}
__device__ __forceinline__ void cp_wait2() {
    asm volatile("cp.async.wait_group 2;" ::: "memory");
}

__device__ __forceinline__ void ldsm4(uint32_t& r0, uint32_t& r1, uint32_t& r2,
                                      uint32_t& r3, uint32_t addr) {
    asm volatile("ldmatrix.sync.aligned.m8n8.x4.shared.b16 {%0,%1,%2,%3}, [%4];"
                 : "=r"(r0), "=r"(r1), "=r"(r2), "=r"(r3) : "r"(addr));
}

__device__ __forceinline__ void mma_f16(float* c, const uint32_t* a,
                                        uint32_t b0, uint32_t b1) {
    asm volatile(
        "mma.sync.aligned.m16n8k16.row.col.f32.f16.f16.f32 "
        "{%0,%1,%2,%3}, {%4,%5,%6,%7}, {%8,%9}, {%0,%1,%2,%3};"
        : "+f"(c[0]), "+f"(c[1]), "+f"(c[2]), "+f"(c[3])
        : "r"(a[0]), "r"(a[1]), "r"(a[2]), "r"(a[3]), "r"(b0), "r"(b1));
}

// ---------------- tensor-core GEMM: fp16 hi/lo x W(fp16), 2 MMA products ------
// Block: 128(M) x 128(N), BK=32, 256 threads = 8 warps as 4(M) x 2(N)
// (warp tile 32x64: fewer ldsm per MMA than 2x4).
// Grid is (6, mtiles): the 6 mat/n-half blocks sharing one m-tile are launch-
// adjacent -> co-resident -> A tiles hit L2 instead of re-reading DRAM.
// A smem row = [hi 64B | lo 64B] = 128B, SW128 xor swizzle.
// B smem row = 64B (single fp16), 64B xor swizzle.
// 4-stage cp.async pipeline; 2 CTAs/SM (96KB smem, 128 regs).
#define STAGE_BYTES 24576   /* A 16KB + B 8KB */
#define GSMEM_TOTAL (4 * STAGE_BYTES)

__global__ __launch_bounds__(256, 2) void gemm_tc_kernel(
    int layer, const int* __restrict__ edge_nodes)
{
    extern __shared__ char smem[];
    const uint32_t smem_base = smem_u32(smem);

    const int tid  = threadIdx.x;
    const int lane = tid & 31;
    const int w    = tid >> 5;
    const int wm   = w >> 1;         // 0..3 -> 32 M-rows each
    const int wn   = w & 1;          // 0..1 -> 64 N-cols each

    const int mat = blockIdx.x >> 1;
    const int n0  = (blockIdx.x & 1) * 128;
    const int m0  = blockIdx.y * 128;

    const __half* Wt = g_wt + (size_t)(layer * 3 + mat) * 65536 + (size_t)n0 * 256;

    // ldmatrix lane address decomposition (same pattern for A and B)
    const int g     = lane >> 3;                       // 0..3
    const int rlane = (lane & 7) + ((g & 1) << 3);     // row-in-frag 0..15
    const int khalf = g >> 1;                          // 0..1 (k 16B chunk)

    float acc[2][8][4];
#pragma unroll
    for (int mi = 0; mi < 2; mi++)
#pragma unroll
        for (int nj = 0; nj < 8; nj++)
#pragma unroll
            for (int r = 0; r < 4; r++) acc[mi][nj][r] = 0.f;

    // ---- tile loader: stage s, K-chunk kc (kc in 0..7, 32 cols each) ----
    auto load_tiles = [&](int s, int kc) {
        uint32_t sA = smem_base + s * STAGE_BYTES;
        uint32_t sB = sA + 16384;
#pragma unroll
        for (int i = 0; i < 4; i++) {               // A: 1024 16B chunks
            int ch  = tid + i * 256;
            int row = ch >> 3, pos = ch & 7;        // pos 0-3 hi, 4-7 lo
            int split = pos >> 2, p4 = pos & 3;
            int grow = m0 + row;
            bool v = (grow < NE);
            int r = v ? grow : 0;
            const __half* src =
                (split ? g_x_lo : g_x_hi) + (size_t)r * F + kc * 32 + p4 * 8;
            uint32_t dst = sA + row * 128 + ((pos ^ (row & 7)) << 4);
            cp16(dst, src, v);
        }
#pragma unroll
        for (int i = 0; i < 2; i++) {               // B: 512 16B chunks
            int ch  = tid + i * 256;
            int row = ch >> 2, pos = ch & 3;        // 64B rows
            const __half* src = Wt + (size_t)row * 256 + kc * 32 + pos * 8;
            uint32_t dst = sB + row * 64 + ((pos ^ ((row >> 1) & 3)) << 4);
            cp16(dst, src, true);
        }
    };

    load_tiles(0, 0); cp_commit();
    load_tiles(1, 1); cp_commit();
    load_tiles(2, 2); cp_commit();

    for (int kc = 0; kc < 8; kc++) {
        cp_wait2();
        __syncthreads();

        // prefetch kc+3 into the stage consumed in the previous iteration
        if (kc + 3 < 8) load_tiles((kc + 3) & 3, kc + 3);
        cp_commit();

        const int st = kc & 3;
        uint32_t sA = smem_base + st * STAGE_BYTES;
        uint32_t sB = sA + 16384;

#pragma unroll
        for (int ks = 0; ks < 2; ks++) {
            const int cH = ks * 2 + khalf;         // 16B k-chunk idx 0..3

            // B fragments: 4 ldsm cover the warp's 64 N-cols (16 regs)
            uint32_t bh[4][4];
#pragma unroll
            for (int j = 0; j < 4; j++) {
                int row = wn * 64 + j * 16 + rlane;
                ldsm4(bh[j][0], bh[j][1], bh[j][2], bh[j][3],
                      sB + row * 64 + ((cH ^ ((row >> 1) & 3)) << 4));
            }

            // A fragments per mi (hi+lo), reused across 8 N-frags
#pragma unroll
            for (int mi = 0; mi < 2; mi++) {
                int row = wm * 32 + mi * 16 + rlane;
                uint32_t base = sA + row * 128;
                uint32_t ah[4], al[4];
                ldsm4(ah[0], ah[1], ah[2], ah[3],
                      base + ((cH ^ (row & 7)) << 4));
                ldsm4(al[0], al[1], al[2], al[3],
                      base + (((cH + 4) ^ (row & 7)) << 4));
#pragma unroll
                for (int nj = 0; nj < 8; nj++) {
                    int j = nj >> 1, o = nj & 1;
                    mma_f16(acc[mi][nj], ah, bh[j][o], bh[j][o + 2]); // hi * w
                    mma_f16(acc[mi][nj], al, bh[j][o], bh[j][o + 2]); // lo * w
                }
            }
        }
        __syncthreads();
    }

    const int crow = lane >> 2;
    const int ccol = (lane & 3) * 2;

    if (mat == 0) {
        // ---- fused B1 scatter: z[u] -= y0, z[v] += y0 (red.v4 via lane pair) --
#pragma unroll
        for (int mi = 0; mi < 2; mi++) {
            int r0 = m0 + wm * 32 + mi * 16 + crow;
            int r1 = r0 + 8;
            int u0 = 0, v0 = 0, u1 = 0, v1 = 0;
            if (r0 < NE) { u0 = edge_nodes[2 * r0]; v0 = edge_nodes[2 * r0 + 1]; }
            if (r1 < NE) { u1 = edge_nodes[2 * r1]; v1 = edge_nodes[2 * r1 + 1]; }
            int gc = n0 + wn * 64 + (lane & 2) * 2;  // float4 col base (per pair)
#pragma unroll
            for (int nj = 0; nj < 8; nj++) {
                float x0 = acc[mi][nj][0], y0 = acc[mi][nj][1];
                float x1 = acc[mi][nj][2], y1 = acc[mi][nj][3];
                float px0 = __shfl_xor_sync(0xffffffffu, x0, 1);
                float py0 = __shfl_xor_sync(0xffffffffu, y0, 1);
                float px1 = __shfl_xor_sync(0xffffffffu, x1, 1);
                float py1 = __shfl_xor_sync(0xffffffffu, y1, 1);
                if (!(lane & 1)) {
                    int c = gc + nj * 8;
                    if (r0 < NE) {
                        float4 q = make_float4(x0, y0, px0, py0);
                        red_add_f32x4(&g_z[(size_t)u0 * F + c],
                                      make_float4(-q.x, -q.y, -q.z, -q.w));
                        red_add_f32x4(&g_z[(size_t)v0 * F + c], q);
                    }
                    if (r1 < NE) {
                        float4 q = make_float4(x1, y1, px1, py1);
                        red_add_f32x4(&g_z[(size_t)u1 * F + c],
                                      make_float4(-q.x, -q.y, -q.z, -q.w));
                        red_add_f32x4(&g_z[(size_t)v1 * F + c], q);
                    }
                }
            }
        }
    } else {
        float* OUT = (mat == 1) ? g_acc : g_y2;
#pragma unroll
        for (int mi = 0; mi < 2; mi++) {
#pragma unroll
            for (int nj = 0; nj < 8; nj++) {
                int gr = m0 + wm * 32 + mi * 16 + crow;
                int gc = n0 + wn * 64 + nj * 8 + ccol;
                if (gr < NE)
                    *(float2*)&OUT[(size_t)gr * F + gc] =
                        make_float2(acc[mi][nj][0], acc[mi][nj][1]);
                if (gr + 8 < NE)
                    *(float2*)&OUT[(size_t)(gr + 8) * F + gc] =
                        make_float2(acc[mi][nj][2], acc[mi][nj][3]);
            }
        }
    }
}

// ---------------- fp16 split conversion -----------------------------------------
__device__ __forceinline__ void split2h(float v, __half& h, __half& l) {
    h = __float2half_rn(v);
    l = __float2half_rn(v - __half2float(h));
}

__device__ __forceinline__ void store_split4(size_t off, float4 r) {
    __half h[4], l[4];
    split2h(r.x, h[0], l[0]); split2h(r.y, h[1], l[1]);
    split2h(r.z, h[2], l[2]); split2h(r.w, h[3], l[3]);
    *(uint2*)&g_x_hi[off] = *(uint2*)h;
    *(uint2*)&g_x_lo[off] = *(uint2*)l;
}

__global__ void convert_x_kernel(const float* __restrict__ x) {
    int t = blockIdx.x * 256 + threadIdx.x;
    if (t >= NE * 64) return;
    int e = t >> 6, c = (t & 63) * 4;
    float4 v = *(const float4*)&x[(size_t)e * F + c];
    store_split4((size_t)e * F + c, v);
}

// all layers at once: g_wt[l*3+mat][n][k] = fp16(W_mat^l[k][n])
__global__ void convert_w_kernel(const float* __restrict__ W0,
                                 const float* __restrict__ W1,
                                 const float* __restrict__ W2) {
    int t = blockIdx.x * 256 + threadIdx.x;
    if (t >= NLAYERS * 3 * F * F) return;
    int lm = t >> 16, r = t & 65535, n = r >> 8, k = r & 255;
    int l = lm / 3, mat = lm % 3;
    const float* W = ((mat == 0) ? W0 : (mat == 1) ? W1 : W2) + (size_t)l * F * F;
    g_wt[t] = __float2half_rn(W[k * F + n]);
}

// ---------------- graph ops ----------------------------------------------------
__global__ void zero_z_kernel() {
    int i = blockIdx.x * 256 + threadIdx.x;
    if (i < NN * F / 4) ((float4*)g_z)[i] = make_float4(0.f, 0.f, 0.f, 0.f);
}

// fused B2: w = sum_k s_k * y2[e_k]; acc[e_k] += s_k * w   (no round trip)
__global__ void b2_fused_kernel(const int* __restrict__ tri_edges,
                                const int* __restrict__ tri_signs) {
    int t = blockIdx.x * 256 + threadIdx.x;
    if (t >= NT * 64) return;
    int tri = t >> 6, c = (t & 63) * 4;
    int e0 = tri_edges[3 * tri], e1 = tri_edges[3 * tri + 1], e2 = tri_edges[3 * tri + 2];
    float s0 = (float)tri_signs[3 * tri];
    float s1 = (float)tri_signs[3 * tri + 1];
    float s2 = (float)tri_signs[3 * tri + 2];
    float4 v0 = *(const float4*)&g_y2[(size_t)e0 * F + c];
    float4 v1 = *(const float4*)&g_y2[(size_t)e1 * F + c];
    float4 v2 = *(const float4*)&g_y2[(size_t)e2 * F + c];
    float4 wv = make_float4(s0 * v0.x + s1 * v1.x + s2 * v2.x,
                            s0 * v0.y + s1 * v1.y + s2 * v2.y,
                            s0 * v0.z + s1 * v1.z + s2 * v2.z,
                            s0 * v0.w + s1 * v1.w + s2 * v2.w);
    red_add_f32x4(&g_acc[(size_t)e0 * F + c],
                  make_float4(s0 * wv.x, s0 * wv.y, s0 * wv.z, s0 * wv.w));
    red_add_f32x4(&g_acc[(size_t)e1 * F + c],
                  make_float4(s1 * wv.x, s1 * wv.y, s1 * wv.z, s1 * wv.w));
    red_add_f32x4(&g_acc[(size_t)e2 * F + c],
                  make_float4(s2 * wv.x, s2 * wv.y, s2 * wv.z, s2 * wv.w));
}

// x_new = relu(acc + z[v] - z[u]); writes fp16 hi/lo splits (fp32 on last layer)
__global__ void fuse_relu_kernel(const int* __restrict__ edge_nodes, int write_f32) {
    int t = blockIdx.x * 256 + threadIdx.x;
    if (t >= NE * 64) return;
    int e = t >> 6, c = (t & 63) * 4;
    int u = edge_nodes[2 * e], v = edge_nodes[2 * e + 1];
    float4 a  = *(const float4*)&g_acc[(size_t)e * F + c];
    float4 zu = *(const float4*)&g_z[(size_t)u * F + c];
    float4 zv = *(const float4*)&g_z[(size_t)v * F + c];
    float4 r = make_float4(fmaxf(a.x + zv.x - zu.x, 0.f),
                           fmaxf(a.y + zv.y - zu.y, 0.f),
                           fmaxf(a.z + zv.z - zu.z, 0.f),
                           fmaxf(a.w + zv.w - zu.w, 0.f));
    size_t off = (size_t)e * F + c;
    if (write_f32) {
        *(float4*)&g_x[off] = r;
    } else {
        store_split4(off, r);
    }
}

__global__ void zero_out_kernel(float* out) {
    int i = blockIdx.x * 256 + threadIdx.x;
    if (i < NN) out[i] = 0.f;
}

__global__ void gemv_scatter_kernel(const float* __restrict__ WL,
                                    const int* __restrict__ edge_nodes,
                                    float* __restrict__ out) {
    __shared__ float ws[F];
    int tid = threadIdx.x;
    ws[tid] = WL[tid];
    __syncthreads();
    int warp = tid >> 5, lane = tid & 31;
    int e = blockIdx.x * 8 + warp;
    if (e >= NE) return;
    float s = 0.f;
#pragma unroll
    for (int j = 0; j < 8; j++) {
        int c = j * 32 + lane;
        s += g_x[(size_t)e * F + c] * ws[c];
    }
#pragma unroll
    for (int o = 16; o; o >>= 1) s += __shfl_xor_sync(0xffffffffu, s, o);
    if (lane == 0) {
        int u = edge_nodes[2 * e], v = edge_nodes[2 * e + 1];
        atomicAdd(&out[u], -s);
        atomicAdd(&out[v], s);
    }
}

// ---------------- launcher ------------------------------------------------------
extern "C" void kernel_launch(void* const* d_in, const int* in_sizes, int n_in,
                              void* d_out, int out_size) {
    const float* x        = (const float*)d_in[0];
    const float* W0s      = (const float*)d_in[1];
    const float* W1s      = (const float*)d_in[2];
    const float* W2s      = (const float*)d_in[3];
    const float* WL       = (const float*)d_in[4];
    const int* edge_nodes = (const int*)d_in[5];
    const int* tri_edges  = (const int*)d_in[6];
    const int* tri_signs  = (const int*)d_in[7];
    float* out            = (float*)d_out;

    cudaFuncSetAttribute(gemm_tc_kernel,
                         cudaFuncAttributeMaxDynamicSharedMemorySize, GSMEM_TOTAL);

    const int mtiles = (NE + 127) / 128;   // 1172

    convert_x_kernel<<<(NE * 64 + 255) / 256, 256>>>(x);
    convert_w_kernel<<<(NLAYERS * 3 * F * F + 255) / 256, 256>>>(W0s, W1s, W2s);

    for (int l = 0; l < NLAYERS; l++) {
        zero_z_kernel<<<(NN * F / 4 + 255) / 256, 256>>>();
        gemm_tc_kernel<<<dim3(6, mtiles), 256, GSMEM_TOTAL>>>(l, edge_nodes);
        b2_fused_kernel<<<(NT * 64 + 255) / 256, 256>>>(tri_edges, tri_signs);
        fuse_relu_kernel<<<(NE * 64 + 255) / 256, 256>>>(edge_nodes,
                                                         (l == NLAYERS - 1) ? 1 : 0);
    }
    zero_out_kernel<<<(NN + 255) / 256, 256>>>(out);
    gemv_scatter_kernel<<<(NE + 7) / 8, 256>>>(WL, edge_nodes, out);
}

// round 15
// speedup vs baseline: 3.2786x; 1.4001x over previous
#include <cuda_runtime.h>
#include <cuda_fp16.h>
#include <cstdint>

#define NE 150000
#define NN 50000
#define NT 100000
#define F  256
#define NLAYERS 4

// ---------------- scratch (allocation-free: __device__ globals) ----------------
__device__ float g_y2[(size_t)NE * F];   // x @ W2
__device__ float g_acc[(size_t)NE * F];  // d1, then += d2 (atomics)
__device__ float g_x[(size_t)NE * F];    // final-layer x (fp32, for GEMV)
__device__ float g_z[(size_t)NN * F];    // node buffer for B1 (atomics)

// fp16 operands: activations single fp16, weights single fp16
__device__ __align__(16) __half g_x_h[(size_t)NE * F];
__device__ __align__(16) __half g_wt[NLAYERS * 3 * F * F];   // [l*3+mat][n][k]

// ---------------- PTX helpers (all sm_80-era, valid on sm_103 baseline) --------
__device__ __forceinline__ void red_add_f32x4(float* addr, float4 v) {
    asm volatile("red.global.add.v4.f32 [%0], {%1,%2,%3,%4};"
                 :: "l"(addr), "f"(v.x), "f"(v.y), "f"(v.z), "f"(v.w) : "memory");
}

__device__ __forceinline__ uint32_t smem_u32(const void* p) {
    uint32_t a;
    asm("{ .reg .u64 t; cvta.to.shared.u64 t, %1; cvt.u32.u64 %0, t; }"
        : "=r"(a) : "l"(p));
    return a;
}

__device__ __forceinline__ void cp16(uint32_t dst, const void* src, bool valid) {
    int sz = valid ? 16 : 0;
    asm volatile("cp.async.ca.shared.global [%0], [%1], 16, %2;"
                 :: "r"(dst), "l"(src), "r"(sz) : "memory");
}
__device__ __forceinline__ void cp_commit() {
    asm volatile("cp.async.commit_group;" ::: "memory");
}
__device__ __forceinline__ void cp_wait2() {
    asm volatile("cp.async.wait_group 2;" ::: "memory");
}

__device__ __forceinline__ void ldsm4(uint32_t& r0, uint32_t& r1, uint32_t& r2,
                                      uint32_t& r3, uint32_t addr) {
    asm volatile("ldmatrix.sync.aligned.m8n8.x4.shared.b16 {%0,%1,%2,%3}, [%4];"
                 : "=r"(r0), "=r"(r1), "=r"(r2), "=r"(r3) : "r"(addr));
}

__device__ __forceinline__ void mma_f16(float* c, const uint32_t* a,
                                        uint32_t b0, uint32_t b1) {
    asm volatile(
        "mma.sync.aligned.m16n8k16.row.col.f32.f16.f16.f32 "
        "{%0,%1,%2,%3}, {%4,%5,%6,%7}, {%8,%9}, {%0,%1,%2,%3};"
        : "+f"(c[0]), "+f"(c[1]), "+f"(c[2]), "+f"(c[3])
        : "r"(a[0]), "r"(a[1]), "r"(a[2]), "r"(a[3]), "r"(b0), "r"(b1));
}

// ---------------- tensor-core GEMM: fp16 x fp16, single product ----------------
// Block: 128(M) x 128(N), BK=32, 256 threads = 8 warps as 4(M) x 2(N).
// Grid (6, mtiles): the 6 mat/n-half blocks per m-tile are launch-adjacent
// -> co-resident -> A tile read from L2, not DRAM.
// A and B smem rows = 64B (single fp16, 32 k-values), 64B xor swizzle.
// 4-stage cp.async pipeline; 2 CTAs/SM.
#define STAGE_BYTES 16384   /* A 8KB + B 8KB */
#define GSMEM_TOTAL (4 * STAGE_BYTES)

__global__ __launch_bounds__(256, 2) void gemm_tc_kernel(
    int layer, const int* __restrict__ edge_nodes)
{
    extern __shared__ char smem[];
    const uint32_t smem_base = smem_u32(smem);

    const int tid  = threadIdx.x;
    const int lane = tid & 31;
    const int w    = tid >> 5;
    const int wm   = w >> 1;         // 0..3 -> 32 M-rows each
    const int wn   = w & 1;          // 0..1 -> 64 N-cols each

    const int mat = blockIdx.x >> 1;
    const int n0  = (blockIdx.x & 1) * 128;
    const int m0  = blockIdx.y * 128;

    const __half* Wt = g_wt + (size_t)(layer * 3 + mat) * 65536 + (size_t)n0 * 256;

    // ldmatrix lane address decomposition (same pattern for A and B)
    const int g     = lane >> 3;                       // 0..3
    const int rlane = (lane & 7) + ((g & 1) << 3);     // row-in-frag 0..15
    const int khalf = g >> 1;                          // 0..1 (k 16B chunk)

    float acc[2][8][4];
#pragma unroll
    for (int mi = 0; mi < 2; mi++)
#pragma unroll
        for (int nj = 0; nj < 8; nj++)
#pragma unroll
            for (int r = 0; r < 4; r++) acc[mi][nj][r] = 0.f;

    // ---- tile loader: stage s, K-chunk kc (kc in 0..7, 32 cols each) ----
    auto load_tiles = [&](int s, int kc) {
        uint32_t sA = smem_base + s * STAGE_BYTES;
        uint32_t sB = sA + 8192;
#pragma unroll
        for (int i = 0; i < 2; i++) {               // A: 512 16B chunks
            int ch  = tid + i * 256;
            int row = ch >> 2, pos = ch & 3;        // 64B rows
            int grow = m0 + row;
            bool v = (grow < NE);
            int r = v ? grow : 0;
            const __half* src = g_x_h + (size_t)r * F + kc * 32 + pos * 8;
            uint32_t dst = sA + row * 64 + ((pos ^ ((row >> 1) & 3)) << 4);
            cp16(dst, src, v);
        }
#pragma unroll
        for (int i = 0; i < 2; i++) {               // B: 512 16B chunks
            int ch  = tid + i * 256;
            int row = ch >> 2, pos = ch & 3;        // 64B rows
            const __half* src = Wt + (size_t)row * 256 + kc * 32 + pos * 8;
            uint32_t dst = sB + row * 64 + ((pos ^ ((row >> 1) & 3)) << 4);
            cp16(dst, src, true);
        }
    };

    load_tiles(0, 0); cp_commit();
    load_tiles(1, 1); cp_commit();
    load_tiles(2, 2); cp_commit();

    for (int kc = 0; kc < 8; kc++) {
        cp_wait2();
        __syncthreads();

        // prefetch kc+3 into the stage consumed in the previous iteration
        if (kc + 3 < 8) load_tiles((kc + 3) & 3, kc + 3);
        cp_commit();

        const int st = kc & 3;
        uint32_t sA = smem_base + st * STAGE_BYTES;
        uint32_t sB = sA + 8192;

#pragma unroll
        for (int ks = 0; ks < 2; ks++) {
            const int cH = ks * 2 + khalf;         // 16B k-chunk idx 0..3

            // B fragments: 4 ldsm cover the warp's 64 N-cols (16 regs)
            uint32_t bh[4][4];
#pragma unroll
            for (int j = 0; j < 4; j++) {
                int row = wn * 64 + j * 16 + rlane;
                ldsm4(bh[j][0], bh[j][1], bh[j][2], bh[j][3],
                      sB + row * 64 + ((cH ^ ((row >> 1) & 3)) << 4));
            }

            // A fragment per mi, reused across 8 N-frags
#pragma unroll
            for (int mi = 0; mi < 2; mi++) {
                int row = wm * 32 + mi * 16 + rlane;
                uint32_t ah[4];
                ldsm4(ah[0], ah[1], ah[2], ah[3],
                      sA + row * 64 + ((cH ^ ((row >> 1) & 3)) << 4));
#pragma unroll
                for (int nj = 0; nj < 8; nj++) {
                    int j = nj >> 1, o = nj & 1;
                    mma_f16(acc[mi][nj], ah, bh[j][o], bh[j][o + 2]);
                }
            }
        }
        __syncthreads();
    }

    const int crow = lane >> 2;
    const int ccol = (lane & 3) * 2;

    if (mat == 0) {
        // ---- fused B1 scatter: z[u] -= y0, z[v] += y0 (red.v4 via lane pair) --
#pragma unroll
        for (int mi = 0; mi < 2; mi++) {
            int r0 = m0 + wm * 32 + mi * 16 + crow;
            int r1 = r0 + 8;
            int u0 = 0, v0 = 0, u1 = 0, v1 = 0;
            if (r0 < NE) { u0 = edge_nodes[2 * r0]; v0 = edge_nodes[2 * r0 + 1]; }
            if (r1 < NE) { u1 = edge_nodes[2 * r1]; v1 = edge_nodes[2 * r1 + 1]; }
            int gc = n0 + wn * 64 + (lane & 2) * 2;  // float4 col base (per pair)
#pragma unroll
            for (int nj = 0; nj < 8; nj++) {
                float x0 = acc[mi][nj][0], y0 = acc[mi][nj][1];
                float x1 = acc[mi][nj][2], y1 = acc[mi][nj][3];
                float px0 = __shfl_xor_sync(0xffffffffu, x0, 1);
                float py0 = __shfl_xor_sync(0xffffffffu, y0, 1);
                float px1 = __shfl_xor_sync(0xffffffffu, x1, 1);
                float py1 = __shfl_xor_sync(0xffffffffu, y1, 1);
                if (!(lane & 1)) {
                    int c = gc + nj * 8;
                    if (r0 < NE) {
                        float4 q = make_float4(x0, y0, px0, py0);
                        red_add_f32x4(&g_z[(size_t)u0 * F + c],
                                      make_float4(-q.x, -q.y, -q.z, -q.w));
                        red_add_f32x4(&g_z[(size_t)v0 * F + c], q);
                    }
                    if (r1 < NE) {
                        float4 q = make_float4(x1, y1, px1, py1);
                        red_add_f32x4(&g_z[(size_t)u1 * F + c],
                                      make_float4(-q.x, -q.y, -q.z, -q.w));
                        red_add_f32x4(&g_z[(size_t)v1 * F + c], q);
                    }
                }
            }
        }
    } else {
        float* OUT = (mat == 1) ? g_acc : g_y2;
#pragma unroll
        for (int mi = 0; mi < 2; mi++) {
#pragma unroll
            for (int nj = 0; nj < 8; nj++) {
                int gr = m0 + wm * 32 + mi * 16 + crow;
                int gc = n0 + wn * 64 + nj * 8 + ccol;
                if (gr < NE)
                    *(float2*)&OUT[(size_t)gr * F + gc] =
                        make_float2(acc[mi][nj][0], acc[mi][nj][1]);
                if (gr + 8 < NE)
                    *(float2*)&OUT[(size_t)(gr + 8) * F + gc] =
                        make_float2(acc[mi][nj][2], acc[mi][nj][3]);
            }
        }
    }
}

// ---------------- fp16 conversion ----------------------------------------------
__device__ __forceinline__ void store_h4(size_t off, float4 r) {
    __half h[4];
    h[0] = __float2half_rn(r.x); h[1] = __float2half_rn(r.y);
    h[2] = __float2half_rn(r.z); h[3] = __float2half_rn(r.w);
    *(uint2*)&g_x_h[off] = *(uint2*)h;
}

__global__ void convert_x_kernel(const float* __restrict__ x) {
    int t = blockIdx.x * 256 + threadIdx.x;
    if (t >= NE * 64) return;
    int e = t >> 6, c = (t & 63) * 4;
    float4 v = *(const float4*)&x[(size_t)e * F + c];
    store_h4((size_t)e * F + c, v);
}

// all layers at once: g_wt[l*3+mat][n][k] = fp16(W_mat^l[k][n])
__global__ void convert_w_kernel(const float* __restrict__ W0,
                                 const float* __restrict__ W1,
                                 const float* __restrict__ W2) {
    int t = blockIdx.x * 256 + threadIdx.x;
    if (t >= NLAYERS * 3 * F * F) return;
    int lm = t >> 16, r = t & 65535, n = r >> 8, k = r & 255;
    int l = lm / 3, mat = lm % 3;
    const float* W = ((mat == 0) ? W0 : (mat == 1) ? W1 : W2) + (size_t)l * F * F;
    g_wt[t] = __float2half_rn(W[k * F + n]);
}

// ---------------- graph ops ----------------------------------------------------
__global__ void zero_z_kernel() {
    int i = blockIdx.x * 256 + threadIdx.x;
    if (i < NN * F / 4) ((float4*)g_z)[i] = make_float4(0.f, 0.f, 0.f, 0.f);
}

// fused B2: w = sum_k s_k * y2[e_k]; acc[e_k] += s_k * w   (no round trip)
__global__ void b2_fused_kernel(const int* __restrict__ tri_edges,
                                const int* __restrict__ tri_signs) {
    int t = blockIdx.x * 256 + threadIdx.x;
    if (t >= NT * 64) return;
    int tri = t >> 6, c = (t & 63) * 4;
    int e0 = tri_edges[3 * tri], e1 = tri_edges[3 * tri + 1], e2 = tri_edges[3 * tri + 2];
    float s0 = (float)tri_signs[3 * tri];
    float s1 = (float)tri_signs[3 * tri + 1];
    float s2 = (float)tri_signs[3 * tri + 2];
    float4 v0 = *(const float4*)&g_y2[(size_t)e0 * F + c];
    float4 v1 = *(const float4*)&g_y2[(size_t)e1 * F + c];
    float4 v2 = *(const float4*)&g_y2[(size_t)e2 * F + c];
    float4 wv = make_float4(s0 * v0.x + s1 * v1.x + s2 * v2.x,
                            s0 * v0.y + s1 * v1.y + s2 * v2.y,
                            s0 * v0.z + s1 * v1.z + s2 * v2.z,
                            s0 * v0.w + s1 * v1.w + s2 * v2.w);
    red_add_f32x4(&g_acc[(size_t)e0 * F + c],
                  make_float4(s0 * wv.x, s0 * wv.y, s0 * wv.z, s0 * wv.w));
    red_add_f32x4(&g_acc[(size_t)e1 * F + c],
                  make_float4(s1 * wv.x, s1 * wv.y, s1 * wv.z, s1 * wv.w));
    red_add_f32x4(&g_acc[(size_t)e2 * F + c],
                  make_float4(s2 * wv.x, s2 * wv.y, s2 * wv.z, s2 * wv.w));
}

// x_new = relu(acc + z[v] - z[u]); writes fp16 (fp32 on last layer)
__global__ void fuse_relu_kernel(const int* __restrict__ edge_nodes, int write_f32) {
    int t = blockIdx.x * 256 + threadIdx.x;
    if (t >= NE * 64) return;
    int e = t >> 6, c = (t & 63) * 4;
    int u = edge_nodes[2 * e], v = edge_nodes[2 * e + 1];
    float4 a  = *(const float4*)&g_acc[(size_t)e * F + c];
    float4 zu = *(const float4*)&g_z[(size_t)u * F + c];
    float4 zv = *(const float4*)&g_z[(size_t)v * F + c];
    float4 r = make_float4(fmaxf(a.x + zv.x - zu.x, 0.f),
                           fmaxf(a.y + zv.y - zu.y, 0.f),
                           fmaxf(a.z + zv.z - zu.z, 0.f),
                           fmaxf(a.w + zv.w - zu.w, 0.f));
    size_t off = (size_t)e * F + c;
    if (write_f32) {
        *(float4*)&g_x[off] = r;
    } else {
        store_h4(off, r);
    }
}

__global__ void zero_out_kernel(float* out) {
    int i = blockIdx.x * 256 + threadIdx.x;
    if (i < NN) out[i] = 0.f;
}

__global__ void gemv_scatter_kernel(const float* __restrict__ WL,
                                    const int* __restrict__ edge_nodes,
                                    float* __restrict__ out) {
    __shared__ float ws[F];
    int tid = threadIdx.x;
    ws[tid] = WL[tid];
    __syncthreads();
    int warp = tid >> 5, lane = tid & 31;
    int e = blockIdx.x * 8 + warp;
    if (e >= NE) return;
    float s = 0.f;
#pragma unroll
    for (int j = 0; j < 8; j++) {
        int c = j * 32 + lane;
        s += g_x[(size_t)e * F + c] * ws[c];
    }
#pragma unroll
    for (int o = 16; o; o >>= 1) s += __shfl_xor_sync(0xffffffffu, s, o);
    if (lane == 0) {
        int u = edge_nodes[2 * e], v = edge_nodes[2 * e + 1];
        atomicAdd(&out[u], -s);
        atomicAdd(&out[v], s);
    }
}

// ---------------- launcher ------------------------------------------------------
extern "C" void kernel_launch(void* const* d_in, const int* in_sizes, int n_in,
                              void* d_out, int out_size) {
    const float* x        = (const float*)d_in[0];
    const float* W0s      = (const float*)d_in[1];
    const float* W1s      = (const float*)d_in[2];
    const float* W2s      = (const float*)d_in[3];
    const float* WL       = (const float*)d_in[4];
    const int* edge_nodes = (const int*)d_in[5];
    const int* tri_edges  = (const int*)d_in[6];
    const int* tri_signs  = (const int*)d_in[7];
    float* out            = (float*)d_out;

    cudaFuncSetAttribute(gemm_tc_kernel,
                         cudaFuncAttributeMaxDynamicSharedMemorySize, GSMEM_TOTAL);

    const int mtiles = (NE + 127) / 128;   // 1172

    convert_x_kernel<<<(NE * 64 + 255) / 256, 256>>>(x);
    convert_w_kernel<<<(NLAYERS * 3 * F * F + 255) / 256, 256>>>(W0s, W1s, W2s);

    for (int l = 0; l < NLAYERS; l++) {
        zero_z_kernel<<<(NN * F / 4 + 255) / 256, 256>>>();
        gemm_tc_kernel<<<dim3(6, mtiles), 256, GSMEM_TOTAL>>>(l, edge_nodes);
        b2_fused_kernel<<<(NT * 64 + 255) / 256, 256>>>(tri_edges, tri_signs);
        fuse_relu_kernel<<<(NE * 64 + 255) / 256, 256>>>(edge_nodes,
                                                         (l == NLAYERS - 1) ? 1 : 0);
    }
    zero_out_kernel<<<(NN + 255) / 256, 256>>>(out);
    gemv_scatter_kernel<<<(NE + 7) / 8, 256>>>(WL, edge_nodes, out);
}

// round 16
// speedup vs baseline: 3.5253x; 1.0753x over previous
#include <cuda_runtime.h>
#include <cuda_fp16.h>
#include <cstdint>

#define NE 150000
#define NN 50000
#define NT 100000
#define F  256
#define NLAYERS 4

// ---------------- scratch (allocation-free: __device__ globals) ----------------
__device__ float g_y2[(size_t)NE * F];   // x @ W2
__device__ float g_acc[(size_t)NE * F];  // d1, then += d2 (atomics)
__device__ float g_x[(size_t)NE * F];    // final-layer x (fp32, for GEMV)
__device__ float g_z[(size_t)NN * F];    // node buffer for B1 (atomics)

// fp16 operands: activations single fp16, weights single fp16
__device__ __align__(16) __half g_x_h[(size_t)NE * F];
__device__ __align__(16) __half g_wt[NLAYERS * 3 * F * F];   // [l*3+mat][n][k]

// ---------------- PTX helpers (all sm_80-era, valid on sm_103 baseline) --------
__device__ __forceinline__ void red_add_f32x4(float* addr, float4 v) {
    asm volatile("red.global.add.v4.f32 [%0], {%1,%2,%3,%4};"
                 :: "l"(addr), "f"(v.x), "f"(v.y), "f"(v.z), "f"(v.w) : "memory");
}

__device__ __forceinline__ uint32_t smem_u32(const void* p) {
    uint32_t a;
    asm("{ .reg .u64 t; cvta.to.shared.u64 t, %1; cvt.u32.u64 %0, t; }"
        : "=r"(a) : "l"(p));
    return a;
}

// .cg: bypass L1 allocation (L2-only) — relieves the L1tex bottleneck
__device__ __forceinline__ void cp16(uint32_t dst, const void* src, bool valid) {
    int sz = valid ? 16 : 0;
    asm volatile("cp.async.cg.shared.global [%0], [%1], 16, %2;"
                 :: "r"(dst), "l"(src), "r"(sz) : "memory");
}
__device__ __forceinline__ void cp_commit() {
    asm volatile("cp.async.commit_group;" ::: "memory");
}
__device__ __forceinline__ void cp_wait1() {
    asm volatile("cp.async.wait_group 1;" ::: "memory");
}

__device__ __forceinline__ void ldsm4(uint32_t& r0, uint32_t& r1, uint32_t& r2,
                                      uint32_t& r3, uint32_t addr) {
    asm volatile("ldmatrix.sync.aligned.m8n8.x4.shared.b16 {%0,%1,%2,%3}, [%4];"
                 : "=r"(r0), "=r"(r1), "=r"(r2), "=r"(r3) : "r"(addr));
}

__device__ __forceinline__ void mma_f16(float* c, const uint32_t* a,
                                        uint32_t b0, uint32_t b1) {
    asm volatile(
        "mma.sync.aligned.m16n8k16.row.col.f32.f16.f16.f32 "
        "{%0,%1,%2,%3}, {%4,%5,%6,%7}, {%8,%9}, {%0,%1,%2,%3};"
        : "+f"(c[0]), "+f"(c[1]), "+f"(c[2]), "+f"(c[3])
        : "r"(a[0]), "r"(a[1]), "r"(a[2]), "r"(a[3]), "r"(b0), "r"(b1));
}

// ---------------- tensor-core GEMM: fp16 x fp16, single product ----------------
// Block: 128(M) x 128(N), BK=64, 256 threads = 8 warps as 4(M) x 2(N).
// Grid (6, mtiles): the 6 mat/n-half blocks per m-tile are launch-adjacent
// -> co-resident -> A tile read from L2, not DRAM.
// A and B smem rows = 128B (64 fp16 k-values), SW128 xor swizzle.
// 3-stage cp.async pipeline (BK=64 -> only 4 k-iterations, ONE barrier each);
// 2 CTAs/SM (96KB smem, <=128 regs).
#define STAGE_BYTES 32768   /* A 16KB + B 16KB */
#define GSMEM_TOTAL (3 * STAGE_BYTES)
#define NKC 4               /* 256 / 64 */

__global__ __launch_bounds__(256, 2) void gemm_tc_kernel(
    int layer, const int* __restrict__ edge_nodes)
{
    extern __shared__ char smem[];
    const uint32_t smem_base = smem_u32(smem);

    const int tid  = threadIdx.x;
    const int lane = tid & 31;
    const int w    = tid >> 5;
    const int wm   = w >> 1;         // 0..3 -> 32 M-rows each
    const int wn   = w & 1;          // 0..1 -> 64 N-cols each

    const int mat = blockIdx.x >> 1;
    const int n0  = (blockIdx.x & 1) * 128;
    const int m0  = blockIdx.y * 128;

    const __half* Wt = g_wt + (size_t)(layer * 3 + mat) * 65536 + (size_t)n0 * 256;

    // ldmatrix lane address decomposition (same pattern for A and B)
    const int g     = lane >> 3;                       // 0..3
    const int rlane = (lane & 7) + ((g & 1) << 3);     // row-in-frag 0..15
    const int khalf = g >> 1;                          // 0..1 (k 16B chunk)

    float acc[2][8][4];
#pragma unroll
    for (int mi = 0; mi < 2; mi++)
#pragma unroll
        for (int nj = 0; nj < 8; nj++)
#pragma unroll
            for (int r = 0; r < 4; r++) acc[mi][nj][r] = 0.f;

    // ---- tile loader: stage s, K-chunk kc (kc in 0..3, 64 cols each) ----
    auto load_tiles = [&](int s, int kc) {
        uint32_t sA = smem_base + s * STAGE_BYTES;
        uint32_t sB = sA + 16384;
#pragma unroll
        for (int i = 0; i < 4; i++) {               // A: 1024 16B chunks
            int ch  = tid + i * 256;
            int row = ch >> 3, pos = ch & 7;        // 128B rows, 8 chunks each
            int grow = m0 + row;
            bool v = (grow < NE);
            int r = v ? grow : 0;
            const __half* src = g_x_h + (size_t)r * F + kc * 64 + pos * 8;
            uint32_t dst = sA + row * 128 + ((pos ^ (row & 7)) << 4);
            cp16(dst, src, v);
        }
#pragma unroll
        for (int i = 0; i < 4; i++) {               // B: 1024 16B chunks
            int ch  = tid + i * 256;
            int row = ch >> 3, pos = ch & 7;
            const __half* src = Wt + (size_t)row * 256 + kc * 64 + pos * 8;
            uint32_t dst = sB + row * 128 + ((pos ^ (row & 7)) << 4);
            cp16(dst, src, true);
        }
    };

    load_tiles(0, 0); cp_commit();
    load_tiles(1, 1); cp_commit();

    for (int kc = 0; kc < NKC; kc++) {
        cp_wait1();
        __syncthreads();
        // Single barrier per iteration: it also guarantees all warps finished
        // MMA(kc-1) (program order) before this prefetch overwrites that stage.
        if (kc + 2 < NKC) load_tiles((kc + 2) % 3, kc + 2);
        cp_commit();

        const int st = kc % 3;
        uint32_t sA = smem_base + st * STAGE_BYTES;
        uint32_t sB = sA + 16384;

#pragma unroll
        for (int ks = 0; ks < 4; ks++) {
            const int cH = ks * 2 + khalf;         // 16B k-chunk idx 0..7

            // B fragments: 4 ldsm cover the warp's 64 N-cols (16 regs)
            uint32_t bh[4][4];
#pragma unroll
            for (int j = 0; j < 4; j++) {
                int row = wn * 64 + j * 16 + rlane;
                ldsm4(bh[j][0], bh[j][1], bh[j][2], bh[j][3],
                      sB + row * 128 + ((cH ^ (row & 7)) << 4));
            }

            // A fragment per mi, reused across 8 N-frags
#pragma unroll
            for (int mi = 0; mi < 2; mi++) {
                int row = wm * 32 + mi * 16 + rlane;
                uint32_t ah[4];
                ldsm4(ah[0], ah[1], ah[2], ah[3],
                      sA + row * 128 + ((cH ^ (row & 7)) << 4));
#pragma unroll
                for (int nj = 0; nj < 8; nj++) {
                    int j = nj >> 1, o = nj & 1;
                    mma_f16(acc[mi][nj], ah, bh[j][o], bh[j][o + 2]);
                }
            }
        }
    }
    __syncthreads();   // all MMAs done before epilogue may reuse nothing; keeps
                       // stores ordered after last stage consumption

    const int crow = lane >> 2;
    const int ccol = (lane & 3) * 2;

    if (mat == 0) {
        // ---- fused B1 scatter: z[u] -= y0, z[v] += y0 (red.v4 via lane pair) --
#pragma unroll
        for (int mi = 0; mi < 2; mi++) {
            int r0 = m0 + wm * 32 + mi * 16 + crow;
            int r1 = r0 + 8;
            int u0 = 0, v0 = 0, u1 = 0, v1 = 0;
            if (r0 < NE) { u0 = edge_nodes[2 * r0]; v0 = edge_nodes[2 * r0 + 1]; }
            if (r1 < NE) { u1 = edge_nodes[2 * r1]; v1 = edge_nodes[2 * r1 + 1]; }
            int gc = n0 + wn * 64 + (lane & 2) * 2;  // float4 col base (per pair)
#pragma unroll
            for (int nj = 0; nj < 8; nj++) {
                float x0 = acc[mi][nj][0], y0 = acc[mi][nj][1];
                float x1 = acc[mi][nj][2], y1 = acc[mi][nj][3];
                float px0 = __shfl_xor_sync(0xffffffffu, x0, 1);
                float py0 = __shfl_xor_sync(0xffffffffu, y0, 1);
                float px1 = __shfl_xor_sync(0xffffffffu, x1, 1);
                float py1 = __shfl_xor_sync(0xffffffffu, y1, 1);
                if (!(lane & 1)) {
                    int c = gc + nj * 8;
                    if (r0 < NE) {
                        float4 q = make_float4(x0, y0, px0, py0);
                        red_add_f32x4(&g_z[(size_t)u0 * F + c],
                                      make_float4(-q.x, -q.y, -q.z, -q.w));
                        red_add_f32x4(&g_z[(size_t)v0 * F + c], q);
                    }
                    if (r1 < NE) {
                        float4 q = make_float4(x1, y1, px1, py1);
                        red_add_f32x4(&g_z[(size_t)u1 * F + c],
                                      make_float4(-q.x, -q.y, -q.z, -q.w));
                        red_add_f32x4(&g_z[(size_t)v1 * F + c], q);
                    }
                }
            }
        }
    } else {
        float* OUT = (mat == 1) ? g_acc : g_y2;
#pragma unroll
        for (int mi = 0; mi < 2; mi++) {
#pragma unroll
            for (int nj = 0; nj < 8; nj++) {
                int gr = m0 + wm * 32 + mi * 16 + crow;
                int gc = n0 + wn * 64 + nj * 8 + ccol;
                if (gr < NE)
                    *(float2*)&OUT[(size_t)gr * F + gc] =
                        make_float2(acc[mi][nj][0], acc[mi][nj][1]);
                if (gr + 8 < NE)
                    *(float2*)&OUT[(size_t)(gr + 8) * F + gc] =
                        make_float2(acc[mi][nj][2], acc[mi][nj][3]);
            }
        }
    }
}

// ---------------- fp16 conversion ----------------------------------------------
__device__ __forceinline__ void store_h4(size_t off, float4 r) {
    __half h[4];
    h[0] = __float2half_rn(r.x); h[1] = __float2half_rn(r.y);
    h[2] = __float2half_rn(r.z); h[3] = __float2half_rn(r.w);
    *(uint2*)&g_x_h[off] = *(uint2*)h;
}

__global__ void convert_x_kernel(const float* __restrict__ x) {
    int t = blockIdx.x * 256 + threadIdx.x;
    if (t >= NE * 64) return;
    int e = t >> 6, c = (t & 63) * 4;
    float4 v = *(const float4*)&x[(size_t)e * F + c];
    store_h4((size_t)e * F + c, v);
}

// all layers at once: g_wt[l*3+mat][n][k] = fp16(W_mat^l[k][n])
__global__ void convert_w_kernel(const float* __restrict__ W0,
                                 const float* __restrict__ W1,
                                 const float* __restrict__ W2) {
    int t = blockIdx.x * 256 + threadIdx.x;
    if (t >= NLAYERS * 3 * F * F) return;
    int lm = t >> 16, r = t & 65535, n = r >> 8, k = r & 255;
    int l = lm / 3, mat = lm % 3;
    const float* W = ((mat == 0) ? W0 : (mat == 1) ? W1 : W2) + (size_t)l * F * F;
    g_wt[t] = __float2half_rn(W[k * F + n]);
}

// ---------------- graph ops ----------------------------------------------------
__global__ void zero_z_kernel() {
    int i = blockIdx.x * 256 + threadIdx.x;
    if (i < NN * F / 4) ((float4*)g_z)[i] = make_float4(0.f, 0.f, 0.f, 0.f);
}

// fused B2: w = sum_k s_k * y2[e_k]; acc[e_k] += s_k * w   (no round trip)
__global__ void b2_fused_kernel(const int* __restrict__ tri_edges,
                                const int* __restrict__ tri_signs) {
    int t = blockIdx.x * 256 + threadIdx.x;
    if (t >= NT * 64) return;
    int tri = t >> 6, c = (t & 63) * 4;
    int e0 = tri_edges[3 * tri], e1 = tri_edges[3 * tri + 1], e2 = tri_edges[3 * tri + 2];
    float s0 = (float)tri_signs[3 * tri];
    float s1 = (float)tri_signs[3 * tri + 1];
    float s2 = (float)tri_signs[3 * tri + 2];
    float4 v0 = *(const float4*)&g_y2[(size_t)e0 * F + c];
    float4 v1 = *(const float4*)&g_y2[(size_t)e1 * F + c];
    float4 v2 = *(const float4*)&g_y2[(size_t)e2 * F + c];
    float4 wv = make_float4(s0 * v0.x + s1 * v1.x + s2 * v2.x,
                            s0 * v0.y + s1 * v1.y + s2 * v2.y,
                            s0 * v0.z + s1 * v1.z + s2 * v2.z,
                            s0 * v0.w + s1 * v1.w + s2 * v2.w);
    red_add_f32x4(&g_acc[(size_t)e0 * F + c],
                  make_float4(s0 * wv.x, s0 * wv.y, s0 * wv.z, s0 * wv.w));
    red_add_f32x4(&g_acc[(size_t)e1 * F + c],
                  make_float4(s1 * wv.x, s1 * wv.y, s1 * wv.z, s1 * wv.w));
    red_add_f32x4(&g_acc[(size_t)e2 * F + c],
                  make_float4(s2 * wv.x, s2 * wv.y, s2 * wv.z, s2 * wv.w));
}

// x_new = relu(acc + z[v] - z[u]); writes fp16 (fp32 on last layer)
__global__ void fuse_relu_kernel(const int* __restrict__ edge_nodes, int write_f32) {
    int t = blockIdx.x * 256 + threadIdx.x;
    if (t >= NE * 64) return;
    int e = t >> 6, c = (t & 63) * 4;
    int u = edge_nodes[2 * e], v = edge_nodes[2 * e + 1];
    float4 a  = *(const float4*)&g_acc[(size_t)e * F + c];
    float4 zu = *(const float4*)&g_z[(size_t)u * F + c];
    float4 zv = *(const float4*)&g_z[(size_t)v * F + c];
    float4 r = make_float4(fmaxf(a.x + zv.x - zu.x, 0.f),
                           fmaxf(a.y + zv.y - zu.y, 0.f),
                           fmaxf(a.z + zv.z - zu.z, 0.f),
                           fmaxf(a.w + zv.w - zu.w, 0.f));
    size_t off = (size_t)e * F + c;
    if (write_f32) {
        *(float4*)&g_x[off] = r;
    } else {
        store_h4(off, r);
    }
}

__global__ void zero_out_kernel(float* out) {
    int i = blockIdx.x * 256 + threadIdx.x;
    if (i < NN) out[i] = 0.f;
}

__global__ void gemv_scatter_kernel(const float* __restrict__ WL,
                                    const int* __restrict__ edge_nodes,
                                    float* __restrict__ out) {
    __shared__ float ws[F];
    int tid = threadIdx.x;
    ws[tid] = WL[tid];
    __syncthreads();
    int warp = tid >> 5, lane = tid & 31;
    int e = blockIdx.x * 8 + warp;
    if (e >= NE) return;
    float s = 0.f;
#pragma unroll
    for (int j = 0; j < 8; j++) {
        int c = j * 32 + lane;
        s += g_x[(size_t)e * F + c] * ws[c];
    }
#pragma unroll
    for (int o = 16; o; o >>= 1) s += __shfl_xor_sync(0xffffffffu, s, o);
    if (lane == 0) {
        int u = edge_nodes[2 * e], v = edge_nodes[2 * e + 1];
        atomicAdd(&out[u], -s);
        atomicAdd(&out[v], s);
    }
}

// ---------------- launcher ------------------------------------------------------
extern "C" void kernel_launch(void* const* d_in, const int* in_sizes, int n_in,
                              void* d_out, int out_size) {
    const float* x        = (const float*)d_in[0];
    const float* W0s      = (const float*)d_in[1];
    const float* W1s      = (const float*)d_in[2];
    const float* W2s      = (const float*)d_in[3];
    const float* WL       = (const float*)d_in[4];
    const int* edge_nodes = (const int*)d_in[5];
    const int* tri_edges  = (const int*)d_in[6];
    const int* tri_signs  = (const int*)d_in[7];
    float* out            = (float*)d_out;

    cudaFuncSetAttribute(gemm_tc_kernel,
                         cudaFuncAttributeMaxDynamicSharedMemorySize, GSMEM_TOTAL);

    const int mtiles = (NE + 127) / 128;   // 1172

    convert_x_kernel<<<(NE * 64 + 255) / 256, 256>>>(x);
    convert_w_kernel<<<(NLAYERS * 3 * F * F + 255) / 256, 256>>>(W0s, W1s, W2s);

    for (int l = 0; l < NLAYERS; l++) {
        zero_z_kernel<<<(NN * F / 4 + 255) / 256, 256>>>();
        gemm_tc_kernel<<<dim3(6, mtiles), 256, GSMEM_TOTAL>>>(l, edge_nodes);
        b2_fused_kernel<<<(NT * 64 + 255) / 256, 256>>>(tri_edges, tri_signs);
        fuse_relu_kernel<<<(NE * 64 + 255) / 256, 256>>>(edge_nodes,
                                                         (l == NLAYERS - 1) ? 1 : 0);
    }
    zero_out_kernel<<<(NN + 255) / 256, 256>>>(out);
    gemv_scatter_kernel<<<(NE + 7) / 8, 256>>>(WL, edge_nodes, out);
}